// round 1
// baseline (speedup 1.0000x reference)
#include <cuda_runtime.h>

// ---------------- problem constants ----------------
#define BB 32
#define SS 1024
#define DD 256
#define FF 256
#define TT 8192
#define KDIM 768   // 3 taps * 256 in-channels

// ---------------- scratch (device globals; no allocation allowed) ----------
__device__ float g_Wt1[KDIM * FF];                 // conv1 weights, [kk][o] layout
__device__ float g_Wt2[KDIM * FF];                 // conv2 weights
__device__ float g_h1[(size_t)BB * SS * FF];       // conv1 output (post relu)
__device__ float g_h2[(size_t)BB * SS * FF];       // conv2 output (post relu)
__device__ int   g_cum[BB * SS];
__device__ int   g_mellen[BB];

// ---------------- weight transpose: w[o][i][k] -> Wt[k*256+i][o] ------------
__global__ void transpose_w_kernel(const float* __restrict__ w, float* __restrict__ wt) {
    int idx = blockIdx.x * 256 + threadIdx.x;      // over KDIM*FF
    int o  = idx & 255;
    int kk = idx >> 8;           // 0..767
    int k  = kk >> 8;            // tap 0..2
    int i  = kk & 255;           // in-channel
    wt[idx] = w[o * KDIM + i * 3 + k];
}

// ---------------- per-batch inclusive cumsum of durations -------------------
__global__ void cumsum_kernel(const int* __restrict__ dur,
                              float* __restrict__ out_dur, float* __restrict__ out_mel,
                              int write_dur, int write_mel) {
    __shared__ int sdata[SS];
    int b = blockIdx.x;
    int t = threadIdx.x;
    int v = dur[b * SS + t];
    sdata[t] = v;
    __syncthreads();
    #pragma unroll
    for (int off = 1; off < SS; off <<= 1) {
        int add = (t >= off) ? sdata[t - off] : 0;
        __syncthreads();
        sdata[t] += add;
        __syncthreads();
    }
    g_cum[b * SS + t] = sdata[t];
    if (t == SS - 1) {
        int ml = min(sdata[t], TT);
        g_mellen[b] = ml;
        if (write_mel) out_mel[b] = (float)ml;
    }
    if (write_dur) out_dur[b * SS + t] = (float)v;
}

// ---------------- length regulator gather -----------------------------------
// block = 256 threads = 4 output rows x 64 lanes (float4 per lane)
__global__ void gather_kernel(const float* __restrict__ x, float* __restrict__ out) {
    int b = blockIdx.y;
    int t = blockIdx.x * 4 + (threadIdx.x >> 6);
    int lane = threadIdx.x & 63;
    const int* cum = g_cum + b * SS;
    int ml = g_mellen[b];
    float4 val = make_float4(0.f, 0.f, 0.f, 0.f);
    if (t < ml) {
        // searchsorted(cum, t, side='right'): first idx with cum[idx] > t
        int lo = 0, hi = SS;
        while (lo < hi) {
            int mid = (lo + hi) >> 1;
            if (cum[mid] > t) hi = mid; else lo = mid + 1;
        }
        int src = min(lo, SS - 1);
        val = ((const float4*)(x + ((size_t)b * SS + src) * DD))[lane];
    }
    ((float4*)(out + ((size_t)b * TT + t) * DD))[lane] = val;
}

// ---------------- conv-as-GEMM: H[m][n] = relu(sum_kk X[m,kk]*Wt[kk][n] + bias[n])
// M = 32768 rows (b*1024+s), N = 256, K = 768 (kk = tap*256 + i).
// Block tile 128x64, K-tile 16, thread tile 8x4, 256 threads.
#define BM 128
#define BN 64
#define BK 16

__global__ __launch_bounds__(256) void conv_gemm(
    const float* __restrict__ X, const float* __restrict__ Wt,
    const float* __restrict__ bias, float* __restrict__ H)
{
    __shared__ float As[BK][BM + 4];   // transposed A tile, padded
    __shared__ float Bs[BK][BN];

    int tid = threadIdx.x;
    int tx = tid & 15;
    int ty = tid >> 4;
    int m0 = blockIdx.x * BM;
    int n0 = blockIdx.y * BN;
    int s_base = m0 & (SS - 1);                         // 128 | 1024: block never crosses batches
    const float* Xb = X + ((size_t)(m0 >> 10)) * SS * DD;

    float acc[2][4][4];
    #pragma unroll
    for (int h = 0; h < 2; h++)
        #pragma unroll
        for (int r = 0; r < 4; r++)
            #pragma unroll
            for (int c = 0; c < 4; c++) acc[h][r][c] = 0.f;

    for (int kt = 0; kt < KDIM / BK; kt++) {
        int k  = (kt * BK) >> 8;        // tap (constant across the tile)
        int i0 = (kt * BK) & 255;       // in-channel base

        // -- stage global loads into regs --
        float4 av[2];
        #pragma unroll
        for (int r = 0; r < 2; r++) {
            int f  = tid + r * 256;
            int ml = f >> 2;            // local row 0..127
            int kq = f & 3;             // which float4 of the 16 kk's
            int s  = s_base + ml + k - 1;
            av[r] = make_float4(0.f, 0.f, 0.f, 0.f);
            if (s >= 0 && s < SS)
                av[r] = *(const float4*)(Xb + (size_t)s * DD + i0 + (kq << 2));
        }
        int bkk = tid >> 4;                    // 0..15
        int bn  = (tid & 15) << 2;             // 0..60
        float4 bv = *(const float4*)(Wt + (size_t)(kt * BK + bkk) * FF + n0 + bn);

        __syncthreads();
        #pragma unroll
        for (int r = 0; r < 2; r++) {
            int f  = tid + r * 256;
            int ml = f >> 2;
            int kq = f & 3;
            As[(kq << 2) + 0][ml] = av[r].x;
            As[(kq << 2) + 1][ml] = av[r].y;
            As[(kq << 2) + 2][ml] = av[r].z;
            As[(kq << 2) + 3][ml] = av[r].w;
        }
        *(float4*)&Bs[bkk][bn] = bv;
        __syncthreads();

        #pragma unroll
        for (int kk = 0; kk < BK; kk++) {
            float4 a0 = *(const float4*)&As[kk][ty * 4];
            float4 a1 = *(const float4*)&As[kk][64 + ty * 4];
            float4 b0 = *(const float4*)&Bs[kk][tx * 4];
            float ar[2][4] = {{a0.x, a0.y, a0.z, a0.w}, {a1.x, a1.y, a1.z, a1.w}};
            float br[4]    = {b0.x, b0.y, b0.z, b0.w};
            #pragma unroll
            for (int h = 0; h < 2; h++)
                #pragma unroll
                for (int r = 0; r < 4; r++)
                    #pragma unroll
                    for (int c = 0; c < 4; c++)
                        acc[h][r][c] = fmaf(ar[h][r], br[c], acc[h][r][c]);
        }
    }

    float4 b4 = *(const float4*)(bias + n0 + tx * 4);
    float bb[4] = {b4.x, b4.y, b4.z, b4.w};
    #pragma unroll
    for (int h = 0; h < 2; h++) {
        #pragma unroll
        for (int r = 0; r < 4; r++) {
            int row = m0 + h * 64 + ty * 4 + r;
            float4 o;
            o.x = fmaxf(acc[h][r][0] + bb[0], 0.f);
            o.y = fmaxf(acc[h][r][1] + bb[1], 0.f);
            o.z = fmaxf(acc[h][r][2] + bb[2], 0.f);
            o.w = fmaxf(acc[h][r][3] + bb[3], 0.f);
            *(float4*)(H + (size_t)row * FF + n0 + tx * 4) = o;
        }
    }
}

// ---------------- warp reduction helper -------------------------------------
__device__ __forceinline__ float warp_sum(float v) {
    #pragma unroll
    for (int o = 16; o > 0; o >>= 1) v += __shfl_xor_sync(0xffffffffu, v, o);
    return v;
}

// ---------------- layernorm (in place, input already relu'd) ----------------
// one warp per row of 256, 8 warps per block
__global__ void ln_kernel(float* __restrict__ h, const float* __restrict__ g,
                          const float* __restrict__ bt) {
    int row  = blockIdx.x * 8 + (threadIdx.x >> 5);
    int lane = threadIdx.x & 31;
    float4* p = (float4*)(h + (size_t)row * FF);
    float4 v0 = p[lane];
    float4 v1 = p[lane + 32];
    float s = v0.x + v0.y + v0.z + v0.w + v1.x + v1.y + v1.z + v1.w;
    float mu = warp_sum(s) * (1.f / 256.f);
    float d0x = v0.x - mu, d0y = v0.y - mu, d0z = v0.z - mu, d0w = v0.w - mu;
    float d1x = v1.x - mu, d1y = v1.y - mu, d1z = v1.z - mu, d1w = v1.w - mu;
    float sq = d0x*d0x + d0y*d0y + d0z*d0z + d0w*d0w
             + d1x*d1x + d1y*d1y + d1z*d1z + d1w*d1w;
    float var  = warp_sum(sq) * (1.f / 256.f);
    float rstd = rsqrtf(var + 1e-5f);
    float4 g0 = ((const float4*)g)[lane],  g1 = ((const float4*)g)[lane + 32];
    float4 b0 = ((const float4*)bt)[lane], b1 = ((const float4*)bt)[lane + 32];
    float4 o0, o1;
    o0.x = d0x * rstd * g0.x + b0.x;  o0.y = d0y * rstd * g0.y + b0.y;
    o0.z = d0z * rstd * g0.z + b0.z;  o0.w = d0w * rstd * g0.w + b0.w;
    o1.x = d1x * rstd * g1.x + b1.x;  o1.y = d1y * rstd * g1.y + b1.y;
    o1.z = d1z * rstd * g1.z + b1.z;  o1.w = d1w * rstd * g1.w + b1.w;
    p[lane] = o0;
    p[lane + 32] = o1;
}

// ---------------- layernorm2 + linear head -> log_dur -----------------------
__global__ void ln2_linear_kernel(const float* __restrict__ h, const float* __restrict__ g,
                                  const float* __restrict__ bt, const float* __restrict__ lw,
                                  const float* __restrict__ lb,
                                  const unsigned char* __restrict__ mask,
                                  float* __restrict__ out_ld) {
    int row  = blockIdx.x * 8 + (threadIdx.x >> 5);
    int lane = threadIdx.x & 31;
    const float4* p = (const float4*)(h + (size_t)row * FF);
    float4 v0 = p[lane];
    float4 v1 = p[lane + 32];
    float s = v0.x + v0.y + v0.z + v0.w + v1.x + v1.y + v1.z + v1.w;
    float mu = warp_sum(s) * (1.f / 256.f);
    float d0x = v0.x - mu, d0y = v0.y - mu, d0z = v0.z - mu, d0w = v0.w - mu;
    float d1x = v1.x - mu, d1y = v1.y - mu, d1z = v1.z - mu, d1w = v1.w - mu;
    float sq = d0x*d0x + d0y*d0y + d0z*d0z + d0w*d0w
             + d1x*d1x + d1y*d1y + d1z*d1z + d1w*d1w;
    float var  = warp_sum(sq) * (1.f / 256.f);
    float rstd = rsqrtf(var + 1e-5f);
    float4 g0 = ((const float4*)g)[lane],  g1 = ((const float4*)g)[lane + 32];
    float4 b0 = ((const float4*)bt)[lane], b1 = ((const float4*)bt)[lane + 32];
    float4 l0 = ((const float4*)lw)[lane], l1 = ((const float4*)lw)[lane + 32];
    float dot =
        (d0x * rstd * g0.x + b0.x) * l0.x + (d0y * rstd * g0.y + b0.y) * l0.y +
        (d0z * rstd * g0.z + b0.z) * l0.z + (d0w * rstd * g0.w + b0.w) * l0.w +
        (d1x * rstd * g1.x + b1.x) * l1.x + (d1y * rstd * g1.y + b1.y) * l1.y +
        (d1z * rstd * g1.z + b1.z) * l1.z + (d1w * rstd * g1.w + b1.w) * l1.w;
    dot = warp_sum(dot);
    if (lane == 0) {
        float val = dot + lb[0];
        if (mask[row]) val = 0.f;   // mask is all-false in this dataset
        out_ld[row] = val;
    }
}

// ---------------- launcher ---------------------------------------------------
extern "C" void kernel_launch(void* const* d_in, const int* in_sizes, int n_in,
                              void* d_out, int out_size) {
    const float*         x        = (const float*)d_in[0];
    const unsigned char* mask     = (const unsigned char*)d_in[1];
    const int*           duration = (const int*)d_in[2];

    // metadata may or may not include the scalar max_len at slot 3
    int w = 3;
    if (n_in >= 14 && in_sizes[3] < 16) w = 4;
    const float* c1w = (const float*)d_in[w + 0];
    const float* c1b = (const float*)d_in[w + 1];
    const float* l1g = (const float*)d_in[w + 2];
    const float* l1b = (const float*)d_in[w + 3];
    const float* c2w = (const float*)d_in[w + 4];
    const float* c2b = (const float*)d_in[w + 5];
    const float* l2g = (const float*)d_in[w + 6];
    const float* l2b = (const float*)d_in[w + 7];
    const float* lw  = (const float*)d_in[w + 8];
    const float* lb  = (const float*)d_in[w + 9];

    float* out = (float*)d_out;
    const long long n_out    = (long long)BB * TT * DD;   // 67108864
    const long long n_ld     = (long long)BB * SS;        // 32768
    int has_ld  = (out_size >= n_out + n_ld);
    int has_dur = (out_size >= n_out + 2 * n_ld);
    int has_mel = (out_size >= n_out + 2 * n_ld + BB);
    float* out_ld  = out + n_out;
    float* out_dur = out_ld + n_ld;
    float* out_mel = out_dur + n_ld;

    void* p;
    cudaGetSymbolAddress(&p, g_Wt1); float* Wt1 = (float*)p;
    cudaGetSymbolAddress(&p, g_Wt2); float* Wt2 = (float*)p;
    cudaGetSymbolAddress(&p, g_h1);  float* h1  = (float*)p;
    cudaGetSymbolAddress(&p, g_h2);  float* h2  = (float*)p;

    // length-regulator path
    cumsum_kernel<<<BB, SS>>>(duration, out_dur, out_mel, has_dur, has_mel);
    gather_kernel<<<dim3(TT / 4, BB), 256>>>(x, out);

    // duration-predictor path (only needed if log_dur is part of the output)
    if (has_ld) {
        transpose_w_kernel<<<KDIM, 256>>>(c1w, Wt1);
        transpose_w_kernel<<<KDIM, 256>>>(c2w, Wt2);
        conv_gemm<<<dim3(BB * SS / BM, FF / BN), 256>>>(x, Wt1, c1b, h1);
        ln_kernel<<<BB * SS / 8, 256>>>(h1, l1g, l1b);
        conv_gemm<<<dim3(BB * SS / BM, FF / BN), 256>>>(h1, Wt2, c2b, h2);
        ln2_linear_kernel<<<BB * SS / 8, 256>>>(h2, l2g, l2b, lw, lb, mask, out_ld);
    }
}

// round 3
// speedup vs baseline: 1.9446x; 1.9446x over previous
#include <cuda_runtime.h>
#include <cuda_bf16.h>
#include <stdint.h>

// ---------------- problem constants ----------------
#define BB 32
#define SS 1024
#define DD 256
#define FF 256
#define TT 8192
#define KDIM 768
#define NT 24          // K tiles of 32

// ---------------- scratch (device globals; no allocation allowed) ----------
__device__ __nv_bfloat16 g_xh[(size_t)BB * SS * DD];
__device__ __nv_bfloat16 g_xl[(size_t)BB * SS * DD];
__device__ __nv_bfloat16 g_h1h[(size_t)BB * SS * FF];
__device__ __nv_bfloat16 g_h1l[(size_t)BB * SS * FF];
__device__ float g_h1f[(size_t)BB * SS * FF];
__device__ float g_h2f[(size_t)BB * SS * FF];
__device__ __nv_bfloat16 g_W1h[FF * KDIM];
__device__ __nv_bfloat16 g_W1l[FF * KDIM];
__device__ __nv_bfloat16 g_W2h[FF * KDIM];
__device__ __nv_bfloat16 g_W2l[FF * KDIM];
__device__ int g_cum[BB * SS];
__device__ int g_mellen[BB];

// ---------------- small helpers ----------------------------------------------
__device__ __forceinline__ uint32_t smem_u32(const void* p) {
    uint32_t a;
    asm("{ .reg .u64 t; cvta.to.shared.u64 t, %1; cvt.u32.u64 %0, t; }" : "=r"(a) : "l"(p));
    return a;
}
__device__ __forceinline__ void split_bf16(float v, unsigned short& h, unsigned short& l) {
    __nv_bfloat16 hi = __float2bfloat16(v);
    __nv_bfloat16 lo = __float2bfloat16(v - __bfloat162float(hi));
    h = __bfloat16_as_ushort(hi);
    l = __bfloat16_as_ushort(lo);
}
__device__ __forceinline__ void ldsm4(uint32_t r[4], uint32_t addr) {
    asm volatile("ldmatrix.sync.aligned.m8n8.x4.shared.b16 {%0,%1,%2,%3}, [%4];"
                 : "=r"(r[0]), "=r"(r[1]), "=r"(r[2]), "=r"(r[3]) : "r"(addr));
}
__device__ __forceinline__ void mma16816(float c[4], const uint32_t a[4],
                                         uint32_t b0, uint32_t b1) {
    asm volatile(
        "mma.sync.aligned.m16n8k16.row.col.f32.bf16.bf16.f32 "
        "{%0,%1,%2,%3}, {%4,%5,%6,%7}, {%8,%9}, {%0,%1,%2,%3};"
        : "+f"(c[0]), "+f"(c[1]), "+f"(c[2]), "+f"(c[3])
        : "r"(a[0]), "r"(a[1]), "r"(a[2]), "r"(a[3]), "r"(b0), "r"(b1));
}
__device__ __forceinline__ void cp16(uint32_t dst, const void* src, uint32_t sz) {
    asm volatile("cp.async.cg.shared.global [%0], [%1], 16, %2;"
                 :: "r"(dst), "l"(src), "r"(sz) : "memory");
}
#define CP_COMMIT() asm volatile("cp.async.commit_group;" ::: "memory")
#define CP_WAIT0()  asm volatile("cp.async.wait_group 0;" ::: "memory")

// swizzled byte offset of 16B chunk (row, kb) inside a [128 rows x 64B] tile
__device__ __forceinline__ uint32_t chunk_off(int row, int kb) {
    return (uint32_t)((row >> 1) * 128 +
                      (((((row & 1) << 2) | kb) ^ ((row >> 1) & 7)) << 4));
}

// ---------------- fp32 -> bf16 (hi,lo) packers ------------------------------
__global__ void split_x_kernel(const float* __restrict__ x,
                               __nv_bfloat16* __restrict__ xh, __nv_bfloat16* __restrict__ xl) {
    int i = blockIdx.x * 256 + threadIdx.x;
    unsigned short h, l;
    split_bf16(x[i], h, l);
    xh[i] = __ushort_as_bfloat16(h);
    xl[i] = __ushort_as_bfloat16(l);
}
// w[o][i][k] -> Wh/Wl[n=o][kk = k*256 + i]
__global__ void split_w_kernel(const float* __restrict__ w,
                               __nv_bfloat16* __restrict__ wh, __nv_bfloat16* __restrict__ wl) {
    int n = blockIdx.x;
    int i = threadIdx.x;
    #pragma unroll
    for (int tap = 0; tap < 3; ++tap) {
        unsigned short h, l;
        split_bf16(w[(size_t)n * KDIM + i * 3 + tap], h, l);
        size_t o = (size_t)n * KDIM + tap * 256 + i;
        wh[o] = __ushort_as_bfloat16(h);
        wl[o] = __ushort_as_bfloat16(l);
    }
}

// ---------------- per-batch inclusive cumsum of durations -------------------
__global__ void cumsum_kernel(const int* __restrict__ dur,
                              float* __restrict__ out_dur, float* __restrict__ out_mel,
                              int write_dur, int write_mel) {
    __shared__ int sdata[SS];
    int b = blockIdx.x;
    int t = threadIdx.x;
    int v = dur[b * SS + t];
    sdata[t] = v;
    __syncthreads();
    #pragma unroll
    for (int off = 1; off < SS; off <<= 1) {
        int add = (t >= off) ? sdata[t - off] : 0;
        __syncthreads();
        sdata[t] += add;
        __syncthreads();
    }
    g_cum[b * SS + t] = sdata[t];
    if (t == SS - 1) {
        int ml = min(sdata[t], TT);
        g_mellen[b] = ml;
        if (write_mel) out_mel[b] = (float)ml;
    }
    if (write_dur) out_dur[b * SS + t] = (float)v;
}

// ---------------- length regulator gather -----------------------------------
__global__ void gather_kernel(const float* __restrict__ x, float* __restrict__ out) {
    int b = blockIdx.y;
    int t = blockIdx.x * 4 + (threadIdx.x >> 6);
    int lane = threadIdx.x & 63;
    const int* cum = g_cum + b * SS;
    int ml = g_mellen[b];
    float4 val = make_float4(0.f, 0.f, 0.f, 0.f);
    if (t < ml) {
        int lo = 0, hi = SS;
        while (lo < hi) {
            int mid = (lo + hi) >> 1;
            if (cum[mid] > t) hi = mid; else lo = mid + 1;
        }
        int src = min(lo, SS - 1);
        val = ((const float4*)(x + ((size_t)b * SS + src) * DD))[lane];
    }
    ((float4*)(out + ((size_t)b * TT + t) * DD))[lane] = val;
}

// ---------------- split-bf16 conv-GEMM via legacy mma.sync -------------------
// H[m][n] = relu( sum_kk A[m][kk]*W[n][kk] + bias[n] )   (fp32 out)
// A im2col: kk = tap*256 + i -> Ah/Al[s + tap - 1][i], zero at batch edges.
// CTA 128x128, BK=32, 8 warps (4m x 2n), warp tile 32x64, 3-term bf16 split.
// smem/stage: Ah 8K | Al 8K | Bh 8K | Bl 8K = 32KB, double buffered = 64KB.
__global__ __launch_bounds__(256, 2) void mma_conv_kernel(
    const __nv_bfloat16* __restrict__ Ah_g, const __nv_bfloat16* __restrict__ Al_g,
    const __nv_bfloat16* __restrict__ Wh_g, const __nv_bfloat16* __restrict__ Wl_g,
    const float* __restrict__ bias, float* __restrict__ H)
{
    extern __shared__ char smem[];
    const uint32_t sb = smem_u32(smem);
    const int tid  = threadIdx.x;
    const int wid  = tid >> 5;
    const int lane = tid & 31;
    const int m0     = blockIdx.x * 128;
    const int n0     = blockIdx.y * 128;
    const int batch  = m0 >> 10;
    const int s_base = m0 & (SS - 1);
    const int warp_m = wid >> 1;      // 0..3, 32 rows each
    const int warp_n = wid & 1;       // 0..1, 64 cols each

    // ---- cp.async per-thread chunk constants (2 chunks x 4 tiles) ----
    const int c0 = tid, c1 = tid + 256;
    const int rowC0 = c0 >> 2, kbC0 = c0 & 3;
    const int rowC1 = c1 >> 2, kbC1 = c1 & 3;
    const uint32_t dst0 = chunk_off(rowC0, kbC0);
    const uint32_t dst1 = chunk_off(rowC1, kbC1);
    const __nv_bfloat16* Ah_b = Ah_g + ((size_t)batch << 10) * DD;
    const __nv_bfloat16* Al_b = Al_g + ((size_t)batch << 10) * DD;

    // ---- ldmatrix per-thread swizzled offsets ----
    uint32_t aoff[2][2], boff[4][2];
    #pragma unroll
    for (int mt = 0; mt < 2; ++mt) {
        int row = warp_m * 32 + mt * 16 + (lane & 15);
        #pragma unroll
        for (int ks = 0; ks < 2; ++ks)
            aoff[mt][ks] = chunk_off(row, ks * 2 + (lane >> 4));
    }
    #pragma unroll
    for (int jp = 0; jp < 4; ++jp) {
        int row = warp_n * 64 + jp * 16 + ((lane >> 4) << 3) + (lane & 7);
        #pragma unroll
        for (int ks = 0; ks < 2; ++ks)
            boff[jp][ks] = chunk_off(row, ks * 2 + ((lane >> 3) & 1));
    }

    float c[2][8][4];
    #pragma unroll
    for (int mt = 0; mt < 2; ++mt)
        #pragma unroll
        for (int nt = 0; nt < 8; ++nt)
            #pragma unroll
            for (int q = 0; q < 4; ++q) c[mt][nt][q] = 0.f;

    auto issue = [&](int kt, int buf) {
        const int tap = kt >> 3;
        const int i0  = (kt & 7) * 32;
        const uint32_t stb = sb + (uint32_t)buf * 32768u;
        // chunk 0
        {
            int sA = s_base + rowC0 + tap - 1;
            uint32_t szA = ((unsigned)sA < (unsigned)SS) ? 16u : 0u;
            int sAc = min(max(sA, 0), SS - 1);
            size_t aoffg = ((size_t)sAc * DD) + i0 + kbC0 * 8;
            cp16(stb + dst0,          Ah_b + aoffg, szA);
            cp16(stb + 8192u + dst0,  Al_b + aoffg, szA);
            size_t woffg = (size_t)(n0 + rowC0) * KDIM + kt * 32 + kbC0 * 8;
            cp16(stb + 16384u + dst0, Wh_g + woffg, 16u);
            cp16(stb + 24576u + dst0, Wl_g + woffg, 16u);
        }
        // chunk 1
        {
            int sA = s_base + rowC1 + tap - 1;
            uint32_t szA = ((unsigned)sA < (unsigned)SS) ? 16u : 0u;
            int sAc = min(max(sA, 0), SS - 1);
            size_t aoffg = ((size_t)sAc * DD) + i0 + kbC1 * 8;
            cp16(stb + dst1,          Ah_b + aoffg, szA);
            cp16(stb + 8192u + dst1,  Al_b + aoffg, szA);
            size_t woffg = (size_t)(n0 + rowC1) * KDIM + kt * 32 + kbC1 * 8;
            cp16(stb + 16384u + dst1, Wh_g + woffg, 16u);
            cp16(stb + 24576u + dst1, Wl_g + woffg, 16u);
        }
    };

    issue(0, 0);
    CP_COMMIT();

    for (int kt = 0; kt < NT; ++kt) {
        CP_WAIT0();
        __syncthreads();
        if (kt + 1 < NT) issue(kt + 1, (kt + 1) & 1);
        CP_COMMIT();

        const uint32_t stb = sb + (uint32_t)(kt & 1) * 32768u;
        #pragma unroll
        for (int ks = 0; ks < 2; ++ks) {
            uint32_t ah[2][4], al[2][4];
            ldsm4(ah[0], stb + aoff[0][ks]);
            ldsm4(ah[1], stb + aoff[1][ks]);
            ldsm4(al[0], stb + 8192u + aoff[0][ks]);
            ldsm4(al[1], stb + 8192u + aoff[1][ks]);
            #pragma unroll
            for (int jp = 0; jp < 4; ++jp) {
                uint32_t bh[4], bl[4];
                ldsm4(bh, stb + 16384u + boff[jp][ks]);
                ldsm4(bl, stb + 24576u + boff[jp][ks]);
                const int nA = 2 * jp, nB = 2 * jp + 1;
                // hh
                mma16816(c[0][nA], ah[0], bh[0], bh[1]);
                mma16816(c[1][nA], ah[1], bh[0], bh[1]);
                mma16816(c[0][nB], ah[0], bh[2], bh[3]);
                mma16816(c[1][nB], ah[1], bh[2], bh[3]);
                // hl
                mma16816(c[0][nA], ah[0], bl[0], bl[1]);
                mma16816(c[1][nA], ah[1], bl[0], bl[1]);
                mma16816(c[0][nB], ah[0], bl[2], bl[3]);
                mma16816(c[1][nB], ah[1], bl[2], bl[3]);
                // lh
                mma16816(c[0][nA], al[0], bh[0], bh[1]);
                mma16816(c[1][nA], al[1], bh[0], bh[1]);
                mma16816(c[0][nB], al[0], bh[2], bh[3]);
                mma16816(c[1][nB], al[1], bh[2], bh[3]);
            }
        }
    }

    // ---- epilogue: +bias, relu, store fp32 ----
    const int g   = lane >> 2;
    const int tig = lane & 3;
    #pragma unroll
    for (int nt = 0; nt < 8; ++nt) {
        const int col = n0 + warp_n * 64 + nt * 8 + tig * 2;
        const float2 bv = *(const float2*)(bias + col);
        #pragma unroll
        for (int mt = 0; mt < 2; ++mt) {
            const int r0 = m0 + warp_m * 32 + mt * 16 + g;
            float2 o0, o1;
            o0.x = fmaxf(c[mt][nt][0] + bv.x, 0.f);
            o0.y = fmaxf(c[mt][nt][1] + bv.y, 0.f);
            o1.x = fmaxf(c[mt][nt][2] + bv.x, 0.f);
            o1.y = fmaxf(c[mt][nt][3] + bv.y, 0.f);
            *(float2*)(H + (size_t)r0 * FF + col)       = o0;
            *(float2*)(H + (size_t)(r0 + 8) * FF + col) = o1;
        }
    }
}

// ---------------- warp reduction --------------------------------------------
__device__ __forceinline__ float warp_sum(float v) {
    #pragma unroll
    for (int o = 16; o > 0; o >>= 1) v += __shfl_xor_sync(0xffffffffu, v, o);
    return v;
}

// ---------------- LN1: fp32 in -> split bf16 out ----------------------------
__global__ void ln1_split_kernel(const float* __restrict__ h, const float* __restrict__ g,
                                 const float* __restrict__ bt,
                                 __nv_bfloat16* __restrict__ oh, __nv_bfloat16* __restrict__ ol) {
    int row  = blockIdx.x * 8 + (threadIdx.x >> 5);
    int lane = threadIdx.x & 31;
    const float4* p = (const float4*)(h + (size_t)row * FF);
    float4 v0 = p[lane];
    float4 v1 = p[lane + 32];
    float s = v0.x + v0.y + v0.z + v0.w + v1.x + v1.y + v1.z + v1.w;
    float mu = warp_sum(s) * (1.f / 256.f);
    float d[8] = {v0.x - mu, v0.y - mu, v0.z - mu, v0.w - mu,
                  v1.x - mu, v1.y - mu, v1.z - mu, v1.w - mu};
    float sq = 0.f;
    #pragma unroll
    for (int i = 0; i < 8; ++i) sq = fmaf(d[i], d[i], sq);
    float var  = warp_sum(sq) * (1.f / 256.f);
    float rstd = rsqrtf(var + 1e-5f);
    float4 g0 = ((const float4*)g)[lane],  g1 = ((const float4*)g)[lane + 32];
    float4 b0 = ((const float4*)bt)[lane], b1 = ((const float4*)bt)[lane + 32];
    float y[8];
    y[0] = d[0] * rstd * g0.x + b0.x;  y[1] = d[1] * rstd * g0.y + b0.y;
    y[2] = d[2] * rstd * g0.z + b0.z;  y[3] = d[3] * rstd * g0.w + b0.w;
    y[4] = d[4] * rstd * g1.x + b1.x;  y[5] = d[5] * rstd * g1.y + b1.y;
    y[6] = d[6] * rstd * g1.z + b1.z;  y[7] = d[7] * rstd * g1.w + b1.w;
    ushort4 uh0, ul0, uh1, ul1;
    split_bf16(y[0], uh0.x, ul0.x); split_bf16(y[1], uh0.y, ul0.y);
    split_bf16(y[2], uh0.z, ul0.z); split_bf16(y[3], uh0.w, ul0.w);
    split_bf16(y[4], uh1.x, ul1.x); split_bf16(y[5], uh1.y, ul1.y);
    split_bf16(y[6], uh1.z, ul1.z); split_bf16(y[7], uh1.w, ul1.w);
    size_t base = (size_t)row * FF;
    *(ushort4*)((unsigned short*)oh + base + lane * 4)       = uh0;
    *(ushort4*)((unsigned short*)oh + base + 128 + lane * 4) = uh1;
    *(ushort4*)((unsigned short*)ol + base + lane * 4)       = ul0;
    *(ushort4*)((unsigned short*)ol + base + 128 + lane * 4) = ul1;
}

// ---------------- LN2 + linear head -> log_dur -------------------------------
__global__ void ln2_linear_kernel(const float* __restrict__ h, const float* __restrict__ g,
                                  const float* __restrict__ bt, const float* __restrict__ lw,
                                  const float* __restrict__ lb,
                                  const unsigned char* __restrict__ mask,
                                  float* __restrict__ out_ld) {
    int row  = blockIdx.x * 8 + (threadIdx.x >> 5);
    int lane = threadIdx.x & 31;
    const float4* p = (const float4*)(h + (size_t)row * FF);
    float4 v0 = p[lane];
    float4 v1 = p[lane + 32];
    float s = v0.x + v0.y + v0.z + v0.w + v1.x + v1.y + v1.z + v1.w;
    float mu = warp_sum(s) * (1.f / 256.f);
    float d[8] = {v0.x - mu, v0.y - mu, v0.z - mu, v0.w - mu,
                  v1.x - mu, v1.y - mu, v1.z - mu, v1.w - mu};
    float sq = 0.f;
    #pragma unroll
    for (int i = 0; i < 8; ++i) sq = fmaf(d[i], d[i], sq);
    float var  = warp_sum(sq) * (1.f / 256.f);
    float rstd = rsqrtf(var + 1e-5f);
    float4 g0 = ((const float4*)g)[lane],  g1 = ((const float4*)g)[lane + 32];
    float4 b0 = ((const float4*)bt)[lane], b1 = ((const float4*)bt)[lane + 32];
    float4 l0 = ((const float4*)lw)[lane], l1 = ((const float4*)lw)[lane + 32];
    float dot =
        (d[0] * rstd * g0.x + b0.x) * l0.x + (d[1] * rstd * g0.y + b0.y) * l0.y +
        (d[2] * rstd * g0.z + b0.z) * l0.z + (d[3] * rstd * g0.w + b0.w) * l0.w +
        (d[4] * rstd * g1.x + b1.x) * l1.x + (d[5] * rstd * g1.y + b1.y) * l1.y +
        (d[6] * rstd * g1.z + b1.z) * l1.z + (d[7] * rstd * g1.w + b1.w) * l1.w;
    dot = warp_sum(dot);
    if (lane == 0) {
        float val = dot + lb[0];
        if (mask[row]) val = 0.f;
        out_ld[row] = val;
    }
}

// ---------------- launcher ---------------------------------------------------
extern "C" void kernel_launch(void* const* d_in, const int* in_sizes, int n_in,
                              void* d_out, int out_size) {
    const float*         x        = (const float*)d_in[0];
    const unsigned char* mask     = (const unsigned char*)d_in[1];
    const int*           duration = (const int*)d_in[2];

    int w = 3;
    if (n_in >= 14 && in_sizes[3] < 16) w = 4;
    const float* c1w = (const float*)d_in[w + 0];
    const float* c1b = (const float*)d_in[w + 1];
    const float* l1g = (const float*)d_in[w + 2];
    const float* l1b = (const float*)d_in[w + 3];
    const float* c2w = (const float*)d_in[w + 4];
    const float* c2b = (const float*)d_in[w + 5];
    const float* l2g = (const float*)d_in[w + 6];
    const float* l2b = (const float*)d_in[w + 7];
    const float* lw  = (const float*)d_in[w + 8];
    const float* lb  = (const float*)d_in[w + 9];

    float* out = (float*)d_out;
    const long long n_out = (long long)BB * TT * DD;
    const long long n_ld  = (long long)BB * SS;
    int has_ld  = (out_size >= n_out + n_ld);
    int has_dur = (out_size >= n_out + 2 * n_ld);
    int has_mel = (out_size >= n_out + 2 * n_ld + BB);
    float* out_ld  = out + n_out;
    float* out_dur = out_ld + n_ld;
    float* out_mel = out_dur + n_ld;

    void* p;
    cudaGetSymbolAddress(&p, g_xh);  __nv_bfloat16* xh  = (__nv_bfloat16*)p;
    cudaGetSymbolAddress(&p, g_xl);  __nv_bfloat16* xl  = (__nv_bfloat16*)p;
    cudaGetSymbolAddress(&p, g_h1h); __nv_bfloat16* h1h = (__nv_bfloat16*)p;
    cudaGetSymbolAddress(&p, g_h1l); __nv_bfloat16* h1l = (__nv_bfloat16*)p;
    cudaGetSymbolAddress(&p, g_h1f); float* h1f = (float*)p;
    cudaGetSymbolAddress(&p, g_h2f); float* h2f = (float*)p;
    cudaGetSymbolAddress(&p, g_W1h); __nv_bfloat16* W1h = (__nv_bfloat16*)p;
    cudaGetSymbolAddress(&p, g_W1l); __nv_bfloat16* W1l = (__nv_bfloat16*)p;
    cudaGetSymbolAddress(&p, g_W2h); __nv_bfloat16* W2h = (__nv_bfloat16*)p;
    cudaGetSymbolAddress(&p, g_W2l); __nv_bfloat16* W2l = (__nv_bfloat16*)p;

    // length-regulator path
    cumsum_kernel<<<BB, SS>>>(duration, out_dur, out_mel, has_dur, has_mel);
    gather_kernel<<<dim3(TT / 4, BB), 256>>>(x, out);

    // duration-predictor path
    if (has_ld) {
        split_x_kernel<<<(BB * SS * DD) / 256, 256>>>(x, xh, xl);
        split_w_kernel<<<FF, 256>>>(c1w, W1h, W1l);
        split_w_kernel<<<FF, 256>>>(c2w, W2h, W2l);

        cudaFuncSetAttribute(mma_conv_kernel,
                             cudaFuncAttributeMaxDynamicSharedMemorySize, 65536);

        mma_conv_kernel<<<dim3(BB * SS / 128, FF / 128), 256, 65536>>>(
            xh, xl, W1h, W1l, c1b, h1f);
        ln1_split_kernel<<<BB * SS / 8, 256>>>(h1f, l1g, l1b, h1h, h1l);
        mma_conv_kernel<<<dim3(BB * SS / 128, FF / 128), 256, 65536>>>(
            h1h, h1l, W2h, W2l, c2b, h2f);
        ln2_linear_kernel<<<BB * SS / 8, 256>>>(h2f, l2g, l2b, lw, lb, mask, out_ld);
    }
}

// round 4
// speedup vs baseline: 2.3414x; 1.2040x over previous
#include <cuda_runtime.h>
#include <cuda_fp16.h>
#include <stdint.h>

// ---------------- problem constants ----------------
#define BB 32
#define SS 1024
#define DD 256
#define FF 256
#define TT 8192
#define KDIM 768
#define NT 24          // K tiles of 32

// ---------------- scratch (device globals; no allocation allowed) ----------
__device__ __half g_xh[(size_t)BB * SS * DD];
__device__ __half g_xl[(size_t)BB * SS * DD];
__device__ __half g_h1h[(size_t)BB * SS * FF];
__device__ __half g_h1l[(size_t)BB * SS * FF];
__device__ float g_h1f[(size_t)BB * SS * FF];
__device__ float g_h2f[(size_t)BB * SS * FF];
__device__ __half g_W1h[FF * KDIM];
__device__ __half g_W2h[FF * KDIM];
__device__ int g_cum[BB * SS];
__device__ int g_mellen[BB];

// ---------------- small helpers ----------------------------------------------
__device__ __forceinline__ uint32_t smem_u32(const void* p) {
    uint32_t a;
    asm("{ .reg .u64 t; cvta.to.shared.u64 t, %1; cvt.u32.u64 %0, t; }" : "=r"(a) : "l"(p));
    return a;
}
__device__ __forceinline__ void split_fp16(float v, __half& h, __half& l) {
    h = __float2half_rn(v);
    l = __float2half_rn(v - __half2float(h));
}
__device__ __forceinline__ void ldsm4(uint32_t r[4], uint32_t addr) {
    asm volatile("ldmatrix.sync.aligned.m8n8.x4.shared.b16 {%0,%1,%2,%3}, [%4];"
                 : "=r"(r[0]), "=r"(r[1]), "=r"(r[2]), "=r"(r[3]) : "r"(addr));
}
__device__ __forceinline__ void mma16816(float c[4], const uint32_t a[4],
                                         uint32_t b0, uint32_t b1) {
    asm volatile(
        "mma.sync.aligned.m16n8k16.row.col.f32.f16.f16.f32 "
        "{%0,%1,%2,%3}, {%4,%5,%6,%7}, {%8,%9}, {%0,%1,%2,%3};"
        : "+f"(c[0]), "+f"(c[1]), "+f"(c[2]), "+f"(c[3])
        : "r"(a[0]), "r"(a[1]), "r"(a[2]), "r"(a[3]), "r"(b0), "r"(b1));
}
__device__ __forceinline__ void cp16(uint32_t dst, const void* src, uint32_t sz) {
    asm volatile("cp.async.cg.shared.global [%0], [%1], 16, %2;"
                 :: "r"(dst), "l"(src), "r"(sz) : "memory");
}
#define CP_COMMIT() asm volatile("cp.async.commit_group;" ::: "memory")
#define CP_WAIT0()  asm volatile("cp.async.wait_group 0;" ::: "memory")

// swizzled byte offset of 16B chunk (row, kb) inside a [rows x 64B] tile
__device__ __forceinline__ uint32_t chunk_off(int row, int kb) {
    return (uint32_t)((row >> 1) * 128 +
                      (((((row & 1) << 2) | kb) ^ ((row >> 1) & 7)) << 4));
}

// ---------------- fp32 -> fp16 (hi,lo) packers ------------------------------
__global__ void split_x_kernel(const float* __restrict__ x,
                               __half* __restrict__ xh, __half* __restrict__ xl) {
    int i = blockIdx.x * 256 + threadIdx.x;
    __half h, l;
    split_fp16(x[i], h, l);
    xh[i] = h;
    xl[i] = l;
}
// w[o][i][k] -> Wh[n=o][kk = k*256 + i]  (hi only)
__global__ void split_w_kernel(const float* __restrict__ w, __half* __restrict__ wh) {
    int n = blockIdx.x;
    int i = threadIdx.x;
    #pragma unroll
    for (int tap = 0; tap < 3; ++tap) {
        float v = w[(size_t)n * KDIM + i * 3 + tap];
        wh[(size_t)n * KDIM + tap * 256 + i] = __float2half_rn(v);
    }
}

// ---------------- per-batch inclusive cumsum of durations -------------------
__global__ void cumsum_kernel(const int* __restrict__ dur,
                              float* __restrict__ out_dur, float* __restrict__ out_mel,
                              int write_dur, int write_mel) {
    __shared__ int sdata[SS];
    int b = blockIdx.x;
    int t = threadIdx.x;
    int v = dur[b * SS + t];
    sdata[t] = v;
    __syncthreads();
    #pragma unroll
    for (int off = 1; off < SS; off <<= 1) {
        int add = (t >= off) ? sdata[t - off] : 0;
        __syncthreads();
        sdata[t] += add;
        __syncthreads();
    }
    g_cum[b * SS + t] = sdata[t];
    if (t == SS - 1) {
        int ml = min(sdata[t], TT);
        g_mellen[b] = ml;
        if (write_mel) out_mel[b] = (float)ml;
    }
    if (write_dur) out_dur[b * SS + t] = (float)v;
}

// ---------------- length regulator gather -----------------------------------
__global__ void gather_kernel(const float* __restrict__ x, float* __restrict__ out) {
    int b = blockIdx.y;
    int t = blockIdx.x * 4 + (threadIdx.x >> 6);
    int lane = threadIdx.x & 63;
    const int* cum = g_cum + b * SS;
    int ml = g_mellen[b];
    float4 val = make_float4(0.f, 0.f, 0.f, 0.f);
    if (t < ml) {
        int lo = 0, hi = SS;
        while (lo < hi) {
            int mid = (lo + hi) >> 1;
            if (cum[mid] > t) hi = mid; else lo = mid + 1;
        }
        int src = min(lo, SS - 1);
        val = ((const float4*)(x + ((size_t)b * SS + src) * DD))[lane];
    }
    ((float4*)(out + ((size_t)b * TT + t) * DD))[lane] = val;
}

// ---------------- split-fp16 conv-GEMM via mma.sync --------------------------
// H[m][n] = relu( sum_kk A[m][kk]*W[n][kk] + bias[n] )   (fp32 out)
// 2-term: C = Ah*Bh + Al*Bh  (A split fp16 hi/lo, B fp16-rounded).
// CTA 128x128, BK=32, 8 warps (4m x 2n), warp tile 32x64.
// smem/stage: Ah 8K | Al 8K | Bh 8K = 24KB, double buffered = 48KB.
__global__ __launch_bounds__(256, 2) void mma_conv_kernel(
    const __half* __restrict__ Ah_g, const __half* __restrict__ Al_g,
    const __half* __restrict__ Wh_g,
    const float* __restrict__ bias, float* __restrict__ H)
{
    extern __shared__ char smem[];
    const uint32_t sb = smem_u32(smem);
    const int tid  = threadIdx.x;
    const int wid  = tid >> 5;
    const int lane = tid & 31;
    const int m0     = blockIdx.x * 128;
    const int n0     = blockIdx.y * 128;
    const int batch  = m0 >> 10;
    const int s_base = m0 & (SS - 1);
    const int warp_m = wid >> 1;      // 0..3, 32 rows each
    const int warp_n = wid & 1;       // 0..1, 64 cols each

    const int c0 = tid, c1 = tid + 256;
    const int rowC0 = c0 >> 2, kbC0 = c0 & 3;
    const int rowC1 = c1 >> 2, kbC1 = c1 & 3;
    const uint32_t dst0 = chunk_off(rowC0, kbC0);
    const uint32_t dst1 = chunk_off(rowC1, kbC1);
    const __half* Ah_b = Ah_g + ((size_t)batch << 10) * DD;
    const __half* Al_b = Al_g + ((size_t)batch << 10) * DD;

    uint32_t aoff[2][2], boff[4][2];
    #pragma unroll
    for (int mt = 0; mt < 2; ++mt) {
        int row = warp_m * 32 + mt * 16 + (lane & 15);
        #pragma unroll
        for (int ks = 0; ks < 2; ++ks)
            aoff[mt][ks] = chunk_off(row, ks * 2 + (lane >> 4));
    }
    #pragma unroll
    for (int jp = 0; jp < 4; ++jp) {
        int row = warp_n * 64 + jp * 16 + ((lane >> 4) << 3) + (lane & 7);
        #pragma unroll
        for (int ks = 0; ks < 2; ++ks)
            boff[jp][ks] = chunk_off(row, ks * 2 + ((lane >> 3) & 1));
    }

    float c[2][8][4];
    #pragma unroll
    for (int mt = 0; mt < 2; ++mt)
        #pragma unroll
        for (int nt = 0; nt < 8; ++nt)
            #pragma unroll
            for (int q = 0; q < 4; ++q) c[mt][nt][q] = 0.f;

    auto issue = [&](int kt, int buf) {
        const int tap = kt >> 3;
        const int i0  = (kt & 7) * 32;
        const uint32_t stb = sb + (uint32_t)buf * 24576u;
        {
            int sA = s_base + rowC0 + tap - 1;
            uint32_t szA = ((unsigned)sA < (unsigned)SS) ? 16u : 0u;
            int sAc = min(max(sA, 0), SS - 1);
            size_t aoffg = ((size_t)sAc * DD) + i0 + kbC0 * 8;
            cp16(stb + dst0,          Ah_b + aoffg, szA);
            cp16(stb + 8192u + dst0,  Al_b + aoffg, szA);
            size_t woffg = (size_t)(n0 + rowC0) * KDIM + kt * 32 + kbC0 * 8;
            cp16(stb + 16384u + dst0, Wh_g + woffg, 16u);
        }
        {
            int sA = s_base + rowC1 + tap - 1;
            uint32_t szA = ((unsigned)sA < (unsigned)SS) ? 16u : 0u;
            int sAc = min(max(sA, 0), SS - 1);
            size_t aoffg = ((size_t)sAc * DD) + i0 + kbC1 * 8;
            cp16(stb + dst1,          Ah_b + aoffg, szA);
            cp16(stb + 8192u + dst1,  Al_b + aoffg, szA);
            size_t woffg = (size_t)(n0 + rowC1) * KDIM + kt * 32 + kbC1 * 8;
            cp16(stb + 16384u + dst1, Wh_g + woffg, 16u);
        }
    };

    issue(0, 0);
    CP_COMMIT();

    for (int kt = 0; kt < NT; ++kt) {
        CP_WAIT0();
        __syncthreads();
        if (kt + 1 < NT) issue(kt + 1, (kt + 1) & 1);
        CP_COMMIT();

        const uint32_t stb = sb + (uint32_t)(kt & 1) * 24576u;
        #pragma unroll
        for (int ks = 0; ks < 2; ++ks) {
            uint32_t ah[2][4], al[2][4];
            ldsm4(ah[0], stb + aoff[0][ks]);
            ldsm4(ah[1], stb + aoff[1][ks]);
            ldsm4(al[0], stb + 8192u + aoff[0][ks]);
            ldsm4(al[1], stb + 8192u + aoff[1][ks]);
            #pragma unroll
            for (int jp = 0; jp < 4; ++jp) {
                uint32_t bh[4];
                ldsm4(bh, stb + 16384u + boff[jp][ks]);
                const int nA = 2 * jp, nB = 2 * jp + 1;
                mma16816(c[0][nA], ah[0], bh[0], bh[1]);
                mma16816(c[1][nA], ah[1], bh[0], bh[1]);
                mma16816(c[0][nB], ah[0], bh[2], bh[3]);
                mma16816(c[1][nB], ah[1], bh[2], bh[3]);
                mma16816(c[0][nA], al[0], bh[0], bh[1]);
                mma16816(c[1][nA], al[1], bh[0], bh[1]);
                mma16816(c[0][nB], al[0], bh[2], bh[3]);
                mma16816(c[1][nB], al[1], bh[2], bh[3]);
            }
        }
    }

    // ---- epilogue: +bias, relu, store fp32 ----
    const int g   = lane >> 2;
    const int tig = lane & 3;
    #pragma unroll
    for (int nt = 0; nt < 8; ++nt) {
        const int col = n0 + warp_n * 64 + nt * 8 + tig * 2;
        const float2 bv = *(const float2*)(bias + col);
        #pragma unroll
        for (int mt = 0; mt < 2; ++mt) {
            const int r0 = m0 + warp_m * 32 + mt * 16 + g;
            float2 o0, o1;
            o0.x = fmaxf(c[mt][nt][0] + bv.x, 0.f);
            o0.y = fmaxf(c[mt][nt][1] + bv.y, 0.f);
            o1.x = fmaxf(c[mt][nt][2] + bv.x, 0.f);
            o1.y = fmaxf(c[mt][nt][3] + bv.y, 0.f);
            *(float2*)(H + (size_t)r0 * FF + col)       = o0;
            *(float2*)(H + (size_t)(r0 + 8) * FF + col) = o1;
        }
    }
}

// ---------------- warp reduction --------------------------------------------
__device__ __forceinline__ float warp_sum(float v) {
    #pragma unroll
    for (int o = 16; o > 0; o >>= 1) v += __shfl_xor_sync(0xffffffffu, v, o);
    return v;
}

// ---------------- LN1: fp32 in -> split fp16 out ----------------------------
__global__ void ln1_split_kernel(const float* __restrict__ h, const float* __restrict__ g,
                                 const float* __restrict__ bt,
                                 __half* __restrict__ oh, __half* __restrict__ ol) {
    int row  = blockIdx.x * 8 + (threadIdx.x >> 5);
    int lane = threadIdx.x & 31;
    const float4* p = (const float4*)(h + (size_t)row * FF);
    float4 v0 = p[lane];
    float4 v1 = p[lane + 32];
    float s = v0.x + v0.y + v0.z + v0.w + v1.x + v1.y + v1.z + v1.w;
    float mu = warp_sum(s) * (1.f / 256.f);
    float d[8] = {v0.x - mu, v0.y - mu, v0.z - mu, v0.w - mu,
                  v1.x - mu, v1.y - mu, v1.z - mu, v1.w - mu};
    float sq = 0.f;
    #pragma unroll
    for (int i = 0; i < 8; ++i) sq = fmaf(d[i], d[i], sq);
    float var  = warp_sum(sq) * (1.f / 256.f);
    float rstd = rsqrtf(var + 1e-5f);
    float4 g0 = ((const float4*)g)[lane],  g1 = ((const float4*)g)[lane + 32];
    float4 b0 = ((const float4*)bt)[lane], b1 = ((const float4*)bt)[lane + 32];
    float y[8];
    y[0] = d[0] * rstd * g0.x + b0.x;  y[1] = d[1] * rstd * g0.y + b0.y;
    y[2] = d[2] * rstd * g0.z + b0.z;  y[3] = d[3] * rstd * g0.w + b0.w;
    y[4] = d[4] * rstd * g1.x + b1.x;  y[5] = d[5] * rstd * g1.y + b1.y;
    y[6] = d[6] * rstd * g1.z + b1.z;  y[7] = d[7] * rstd * g1.w + b1.w;
    __half hh[8], ll[8];
    #pragma unroll
    for (int i = 0; i < 8; ++i) split_fp16(y[i], hh[i], ll[i]);
    size_t base = (size_t)row * FF;
    *(uint2*)(oh + base + lane * 4)       = *(uint2*)&hh[0];
    *(uint2*)(oh + base + 128 + lane * 4) = *(uint2*)&hh[4];
    *(uint2*)(ol + base + lane * 4)       = *(uint2*)&ll[0];
    *(uint2*)(ol + base + 128 + lane * 4) = *(uint2*)&ll[4];
}

// ---------------- LN2 + linear head -> log_dur -------------------------------
__global__ void ln2_linear_kernel(const float* __restrict__ h, const float* __restrict__ g,
                                  const float* __restrict__ bt, const float* __restrict__ lw,
                                  const float* __restrict__ lb,
                                  const unsigned char* __restrict__ mask,
                                  float* __restrict__ out_ld) {
    int row  = blockIdx.x * 8 + (threadIdx.x >> 5);
    int lane = threadIdx.x & 31;
    const float4* p = (const float4*)(h + (size_t)row * FF);
    float4 v0 = p[lane];
    float4 v1 = p[lane + 32];
    float s = v0.x + v0.y + v0.z + v0.w + v1.x + v1.y + v1.z + v1.w;
    float mu = warp_sum(s) * (1.f / 256.f);
    float d[8] = {v0.x - mu, v0.y - mu, v0.z - mu, v0.w - mu,
                  v1.x - mu, v1.y - mu, v1.z - mu, v1.w - mu};
    float sq = 0.f;
    #pragma unroll
    for (int i = 0; i < 8; ++i) sq = fmaf(d[i], d[i], sq);
    float var  = warp_sum(sq) * (1.f / 256.f);
    float rstd = rsqrtf(var + 1e-5f);
    float4 g0 = ((const float4*)g)[lane],  g1 = ((const float4*)g)[lane + 32];
    float4 b0 = ((const float4*)bt)[lane], b1 = ((const float4*)bt)[lane + 32];
    float4 l0 = ((const float4*)lw)[lane], l1 = ((const float4*)lw)[lane + 32];
    float dot =
        (d[0] * rstd * g0.x + b0.x) * l0.x + (d[1] * rstd * g0.y + b0.y) * l0.y +
        (d[2] * rstd * g0.z + b0.z) * l0.z + (d[3] * rstd * g0.w + b0.w) * l0.w +
        (d[4] * rstd * g1.x + b1.x) * l1.x + (d[5] * rstd * g1.y + b1.y) * l1.y +
        (d[6] * rstd * g1.z + b1.z) * l1.z + (d[7] * rstd * g1.w + b1.w) * l1.w;
    dot = warp_sum(dot);
    if (lane == 0) {
        float val = dot + lb[0];
        if (mask[row]) val = 0.f;
        out_ld[row] = val;
    }
}

// ---------------- launcher ---------------------------------------------------
extern "C" void kernel_launch(void* const* d_in, const int* in_sizes, int n_in,
                              void* d_out, int out_size) {
    const float*         x        = (const float*)d_in[0];
    const unsigned char* mask     = (const unsigned char*)d_in[1];
    const int*           duration = (const int*)d_in[2];

    int w = 3;
    if (n_in >= 14 && in_sizes[3] < 16) w = 4;
    const float* c1w = (const float*)d_in[w + 0];
    const float* c1b = (const float*)d_in[w + 1];
    const float* l1g = (const float*)d_in[w + 2];
    const float* l1b = (const float*)d_in[w + 3];
    const float* c2w = (const float*)d_in[w + 4];
    const float* c2b = (const float*)d_in[w + 5];
    const float* l2g = (const float*)d_in[w + 6];
    const float* l2b = (const float*)d_in[w + 7];
    const float* lw  = (const float*)d_in[w + 8];
    const float* lb  = (const float*)d_in[w + 9];

    float* out = (float*)d_out;
    const long long n_out = (long long)BB * TT * DD;
    const long long n_ld  = (long long)BB * SS;
    int has_ld  = (out_size >= n_out + n_ld);
    int has_dur = (out_size >= n_out + 2 * n_ld);
    int has_mel = (out_size >= n_out + 2 * n_ld + BB);
    float* out_ld  = out + n_out;
    float* out_dur = out_ld + n_ld;
    float* out_mel = out_dur + n_ld;

    void* p;
    cudaGetSymbolAddress(&p, g_xh);  __half* xh  = (__half*)p;
    cudaGetSymbolAddress(&p, g_xl);  __half* xl  = (__half*)p;
    cudaGetSymbolAddress(&p, g_h1h); __half* h1h = (__half*)p;
    cudaGetSymbolAddress(&p, g_h1l); __half* h1l = (__half*)p;
    cudaGetSymbolAddress(&p, g_h1f); float* h1f = (float*)p;
    cudaGetSymbolAddress(&p, g_h2f); float* h2f = (float*)p;
    cudaGetSymbolAddress(&p, g_W1h); __half* W1h = (__half*)p;
    cudaGetSymbolAddress(&p, g_W2h); __half* W2h = (__half*)p;

    cumsum_kernel<<<BB, SS>>>(duration, out_dur, out_mel, has_dur, has_mel);

    if (has_ld) {
        split_x_kernel<<<(BB * SS * DD) / 256, 256>>>(x, xh, xl);
        split_w_kernel<<<FF, 256>>>(c1w, W1h);
        split_w_kernel<<<FF, 256>>>(c2w, W2h);

        cudaFuncSetAttribute(mma_conv_kernel,
                             cudaFuncAttributeMaxDynamicSharedMemorySize, 49152);

        mma_conv_kernel<<<dim3(BB * SS / 128, FF / 128), 256, 49152>>>(
            xh, xl, W1h, c1b, h1f);
        ln1_split_kernel<<<BB * SS / 8, 256>>>(h1f, l1g, l1b, h1h, h1l);
        mma_conv_kernel<<<dim3(BB * SS / 128, FF / 128), 256, 49152>>>(
            h1h, h1l, W2h, c2b, h2f);
        ln2_linear_kernel<<<BB * SS / 8, 256>>>(h2f, l2g, l2b, lw, lb, mask, out_ld);
    }

    gather_kernel<<<dim3(TT / 4, BB), 256>>>(x, out);
}

// round 5
// speedup vs baseline: 2.4517x; 1.0471x over previous
#include <cuda_runtime.h>
#include <cuda_fp16.h>
#include <stdint.h>

// ---------------- problem constants ----------------
#define BB 32
#define SS 1024
#define DD 256
#define FF 256
#define TT 8192
#define KDIM 768
#define NT 24          // K tiles of 32

// ---------------- scratch (device globals; no allocation allowed) ----------
__device__ __half g_xh[(size_t)BB * SS * DD];
__device__ __half g_xl[(size_t)BB * SS * DD];
__device__ __half g_h1h[(size_t)BB * SS * FF];
__device__ __half g_h1l[(size_t)BB * SS * FF];
__device__ __half g_W1h[FF * KDIM];
__device__ __half g_W2h[FF * KDIM];
__device__ int g_cum[BB * SS];
__device__ int g_mellen[BB];

// ---------------- small helpers ----------------------------------------------
__device__ __forceinline__ uint32_t smem_u32(const void* p) {
    uint32_t a;
    asm("{ .reg .u64 t; cvta.to.shared.u64 t, %1; cvt.u32.u64 %0, t; }" : "=r"(a) : "l"(p));
    return a;
}
__device__ __forceinline__ void split_fp16(float v, __half& h, __half& l) {
    h = __float2half_rn(v);
    l = __float2half_rn(v - __half2float(h));
}
__device__ __forceinline__ void ldsm4(uint32_t r[4], uint32_t addr) {
    asm volatile("ldmatrix.sync.aligned.m8n8.x4.shared.b16 {%0,%1,%2,%3}, [%4];"
                 : "=r"(r[0]), "=r"(r[1]), "=r"(r[2]), "=r"(r[3]) : "r"(addr));
}
__device__ __forceinline__ void mma16816(float c[4], const uint32_t a[4],
                                         uint32_t b0, uint32_t b1) {
    asm volatile(
        "mma.sync.aligned.m16n8k16.row.col.f32.f16.f16.f32 "
        "{%0,%1,%2,%3}, {%4,%5,%6,%7}, {%8,%9}, {%0,%1,%2,%3};"
        : "+f"(c[0]), "+f"(c[1]), "+f"(c[2]), "+f"(c[3])
        : "r"(a[0]), "r"(a[1]), "r"(a[2]), "r"(a[3]), "r"(b0), "r"(b1));
}
__device__ __forceinline__ void cp16(uint32_t dst, const void* src, uint32_t sz) {
    asm volatile("cp.async.cg.shared.global [%0], [%1], 16, %2;"
                 :: "r"(dst), "l"(src), "r"(sz) : "memory");
}
#define CP_COMMIT() asm volatile("cp.async.commit_group;" ::: "memory")
#define CP_WAIT0()  asm volatile("cp.async.wait_group 0;" ::: "memory")

// swizzled byte offset of 16B chunk (row, kb) inside a [rows x 64B] tile
__device__ __forceinline__ uint32_t chunk_off(int row, int kb) {
    return (uint32_t)((row >> 1) * 128 +
                      (((((row & 1) << 2) | kb) ^ ((row >> 1) & 7)) << 4));
}

// ---------------- fp32 -> fp16 (hi,lo) packers ------------------------------
__global__ void split_x_kernel(const float* __restrict__ x,
                               __half* __restrict__ xh, __half* __restrict__ xl) {
    int i = blockIdx.x * 256 + threadIdx.x;
    __half h, l;
    split_fp16(x[i], h, l);
    xh[i] = h;
    xl[i] = l;
}
// w[o][i][k] -> Wh[n=o][kk = k*256 + i]  (hi only)
__global__ void split_w_kernel(const float* __restrict__ w, __half* __restrict__ wh) {
    int n = blockIdx.x;
    int i = threadIdx.x;
    #pragma unroll
    for (int tap = 0; tap < 3; ++tap) {
        float v = w[(size_t)n * KDIM + i * 3 + tap];
        wh[(size_t)n * KDIM + tap * 256 + i] = __float2half_rn(v);
    }
}

// ---------------- per-batch inclusive cumsum of durations -------------------
__global__ void cumsum_kernel(const int* __restrict__ dur,
                              float* __restrict__ out_dur, float* __restrict__ out_mel,
                              int write_dur, int write_mel) {
    __shared__ int sdata[SS];
    int b = blockIdx.x;
    int t = threadIdx.x;
    int v = dur[b * SS + t];
    sdata[t] = v;
    __syncthreads();
    #pragma unroll
    for (int off = 1; off < SS; off <<= 1) {
        int add = (t >= off) ? sdata[t - off] : 0;
        __syncthreads();
        sdata[t] += add;
        __syncthreads();
    }
    g_cum[b * SS + t] = sdata[t];
    if (t == SS - 1) {
        int ml = min(sdata[t], TT);
        g_mellen[b] = ml;
        if (write_mel) out_mel[b] = (float)ml;
    }
    if (write_dur) out_dur[b * SS + t] = (float)v;
}

// ---------------- length regulator gather -----------------------------------
__global__ void gather_kernel(const float* __restrict__ x, float* __restrict__ out) {
    int b = blockIdx.y;
    int t = blockIdx.x * 4 + (threadIdx.x >> 6);
    int lane = threadIdx.x & 63;
    const int* cum = g_cum + b * SS;
    int ml = g_mellen[b];
    float4 val = make_float4(0.f, 0.f, 0.f, 0.f);
    if (t < ml) {
        int lo = 0, hi = SS;
        while (lo < hi) {
            int mid = (lo + hi) >> 1;
            if (cum[mid] > t) hi = mid; else lo = mid + 1;
        }
        int src = min(lo, SS - 1);
        val = ((const float4*)(x + ((size_t)b * SS + src) * DD))[lane];
    }
    ((float4*)(out + ((size_t)b * TT + t) * DD))[lane] = val;
}

// ---------------- split-fp16 conv-GEMM, full-N tile, fused LN epilogue ------
// CTA 64(M) x 256(N=full F), BK=32, 8 warps (2m x 4n), warp tile 32x64.
// 2-term: C = Ah*Bh + Al*Bh.
// smem/stage: Ah 4K | Al 4K | Bh 16K = 24KB, double buffered = 48KB.
// Epilogue: +bias, relu, row LayerNorm (full row lives in this CTA).
//   MODE 1: write LN output as split fp16 (hi/lo) for next GEMM.
//   MODE 2: dot with lin_w -> log_dur.
template<int MODE>
__global__ __launch_bounds__(256, 2) void mma_conv_ln_kernel(
    const __half* __restrict__ Ah_g, const __half* __restrict__ Al_g,
    const __half* __restrict__ Wh_g,
    const float* __restrict__ bias,
    const float* __restrict__ gamma, const float* __restrict__ beta,
    const float* __restrict__ lw, const float* __restrict__ lb,
    const unsigned char* __restrict__ mask,
    __half* __restrict__ oh, __half* __restrict__ ol,
    float* __restrict__ out_ld)
{
    extern __shared__ char smem[];
    const uint32_t sb = smem_u32(smem);
    const int tid  = threadIdx.x;
    const int wid  = tid >> 5;
    const int lane = tid & 31;
    const int m0     = blockIdx.x * 64;
    const int batch  = m0 >> 10;
    const int s_base = m0 & (SS - 1);
    const int warp_m = wid & 1;       // 0..1, 32 rows each
    const int warp_n = wid >> 1;      // 0..3, 64 cols each

    // cp.async chunk constants: A (64x4 chunks), B (256x4 chunks)
    const int rowA = tid >> 2, kbA = tid & 3;
    const uint32_t dstA = chunk_off(rowA, kbA);
    const __half* Ah_b = Ah_g + ((size_t)batch << 10) * DD;
    const __half* Al_b = Al_g + ((size_t)batch << 10) * DD;

    uint32_t aoff[2][2], boff[4][2];
    #pragma unroll
    for (int mt = 0; mt < 2; ++mt) {
        int row = warp_m * 32 + mt * 16 + (lane & 15);
        #pragma unroll
        for (int ks = 0; ks < 2; ++ks)
            aoff[mt][ks] = chunk_off(row, ks * 2 + (lane >> 4));
    }
    #pragma unroll
    for (int jp = 0; jp < 4; ++jp) {
        int row = warp_n * 64 + jp * 16 + ((lane >> 4) << 3) + (lane & 7);
        #pragma unroll
        for (int ks = 0; ks < 2; ++ks)
            boff[jp][ks] = 8192u + chunk_off(row, ks * 2 + ((lane >> 3) & 1));
    }

    float c[2][8][4];
    #pragma unroll
    for (int mt = 0; mt < 2; ++mt)
        #pragma unroll
        for (int nt = 0; nt < 8; ++nt)
            #pragma unroll
            for (int q = 0; q < 4; ++q) c[mt][nt][q] = 0.f;

    auto issue = [&](int kt, int buf) {
        const int tap = kt >> 3;
        const int i0  = (kt & 7) * 32;
        const uint32_t stb = sb + (uint32_t)buf * 24576u;
        // A hi + lo
        {
            int sA = s_base + rowA + tap - 1;
            uint32_t szA = ((unsigned)sA < (unsigned)SS) ? 16u : 0u;
            int sAc = min(max(sA, 0), SS - 1);
            size_t aoffg = ((size_t)sAc * DD) + i0 + kbA * 8;
            cp16(stb + dstA,          Ah_b + aoffg, szA);
            cp16(stb + 4096u + dstA,  Al_b + aoffg, szA);
        }
        // B: 4 chunks per thread
        #pragma unroll
        for (int j = 0; j < 4; ++j) {
            int id = tid + j * 256;
            int rowB = id >> 2, kbB = id & 3;
            size_t woffg = (size_t)rowB * KDIM + kt * 32 + kbB * 8;
            cp16(stb + 8192u + chunk_off(rowB, kbB), Wh_g + woffg, 16u);
        }
    };

    issue(0, 0);
    CP_COMMIT();

    for (int kt = 0; kt < NT; ++kt) {
        CP_WAIT0();
        __syncthreads();
        if (kt + 1 < NT) issue(kt + 1, (kt + 1) & 1);
        CP_COMMIT();

        const uint32_t stb = sb + (uint32_t)(kt & 1) * 24576u;
        #pragma unroll
        for (int ks = 0; ks < 2; ++ks) {
            uint32_t ah[2][4], al[2][4];
            ldsm4(ah[0], stb + aoff[0][ks]);
            ldsm4(ah[1], stb + aoff[1][ks]);
            ldsm4(al[0], stb + 4096u + aoff[0][ks]);
            ldsm4(al[1], stb + 4096u + aoff[1][ks]);
            #pragma unroll
            for (int jp = 0; jp < 4; ++jp) {
                uint32_t bh[4];
                ldsm4(bh, stb + boff[jp][ks]);
                const int nA = 2 * jp, nB = 2 * jp + 1;
                mma16816(c[0][nA], ah[0], bh[0], bh[1]);
                mma16816(c[1][nA], ah[1], bh[0], bh[1]);
                mma16816(c[0][nB], ah[0], bh[2], bh[3]);
                mma16816(c[1][nB], ah[1], bh[2], bh[3]);
                mma16816(c[0][nA], al[0], bh[0], bh[1]);
                mma16816(c[1][nA], al[1], bh[0], bh[1]);
                mma16816(c[0][nB], al[0], bh[2], bh[3]);
                mma16816(c[1][nB], al[1], bh[2], bh[3]);
            }
        }
    }

    // =================== fused epilogue ===================
    const int g   = lane >> 2;
    const int tig = lane & 3;
    __syncthreads();                    // mainloop smem reads done; reuse smem
    float* red = (float*)smem;          // [0:256) sum, [256:512) sq, [512:768) dot

    // bias + relu (in place), per-thread row partials
    float s_[2][2] = {{0.f, 0.f}, {0.f, 0.f}};
    float q_[2][2] = {{0.f, 0.f}, {0.f, 0.f}};
    #pragma unroll
    for (int nt = 0; nt < 8; ++nt) {
        const int col = warp_n * 64 + nt * 8 + tig * 2;
        const float2 bv = *(const float2*)(bias + col);
        #pragma unroll
        for (int mt = 0; mt < 2; ++mt) {
            float v0 = fmaxf(c[mt][nt][0] + bv.x, 0.f);
            float v1 = fmaxf(c[mt][nt][1] + bv.y, 0.f);
            float v2 = fmaxf(c[mt][nt][2] + bv.x, 0.f);
            float v3 = fmaxf(c[mt][nt][3] + bv.y, 0.f);
            c[mt][nt][0] = v0; c[mt][nt][1] = v1;
            c[mt][nt][2] = v2; c[mt][nt][3] = v3;
            s_[mt][0] += v0 + v1;           s_[mt][1] += v2 + v3;
            q_[mt][0] += v0 * v0 + v1 * v1; q_[mt][1] += v2 * v2 + v3 * v3;
        }
    }
    // quad reduce over tig (lanes g*4 + 0..3)
    #pragma unroll
    for (int off = 1; off <= 2; off <<= 1) {
        #pragma unroll
        for (int mt = 0; mt < 2; ++mt)
            #pragma unroll
            for (int h = 0; h < 2; ++h) {
                s_[mt][h] += __shfl_xor_sync(0xffffffffu, s_[mt][h], off);
                q_[mt][h] += __shfl_xor_sync(0xffffffffu, q_[mt][h], off);
            }
    }
    if (tig == 0) {
        #pragma unroll
        for (int mt = 0; mt < 2; ++mt)
            #pragma unroll
            for (int h = 0; h < 2; ++h) {
                int row = warp_m * 32 + mt * 16 + g + h * 8;
                red[warp_n * 64 + row]        = s_[mt][h];
                red[256 + warp_n * 64 + row]  = q_[mt][h];
            }
    }
    __syncthreads();
    float mu_[2][2], rs_[2][2];
    #pragma unroll
    for (int mt = 0; mt < 2; ++mt)
        #pragma unroll
        for (int h = 0; h < 2; ++h) {
            int row = warp_m * 32 + mt * 16 + g + h * 8;
            float st = red[row] + red[64 + row] + red[128 + row] + red[192 + row];
            float qt = red[256 + row] + red[320 + row] + red[384 + row] + red[448 + row];
            float mu  = st * (1.f / 256.f);
            float var = fmaxf(qt * (1.f / 256.f) - mu * mu, 0.f);
            mu_[mt][h] = mu;
            rs_[mt][h] = rsqrtf(var + 1e-5f);
        }

    if (MODE == 1) {
        #pragma unroll
        for (int nt = 0; nt < 8; ++nt) {
            const int col = warp_n * 64 + nt * 8 + tig * 2;
            const float2 gv = *(const float2*)(gamma + col);
            const float2 bt = *(const float2*)(beta + col);
            #pragma unroll
            for (int mt = 0; mt < 2; ++mt) {
                #pragma unroll
                for (int h = 0; h < 2; ++h) {
                    int row = warp_m * 32 + mt * 16 + g + h * 8;
                    float y0 = (c[mt][nt][2*h]   - mu_[mt][h]) * rs_[mt][h] * gv.x + bt.x;
                    float y1 = (c[mt][nt][2*h+1] - mu_[mt][h]) * rs_[mt][h] * gv.y + bt.y;
                    __half h0, l0, h1, l1;
                    split_fp16(y0, h0, l0);
                    split_fp16(y1, h1, l1);
                    size_t base = (size_t)(m0 + row) * FF + col;
                    *(__half2*)(oh + base) = __halves2half2(h0, h1);
                    *(__half2*)(ol + base) = __halves2half2(l0, l1);
                }
            }
        }
    } else {
        float d_[2][2] = {{0.f, 0.f}, {0.f, 0.f}};
        #pragma unroll
        for (int nt = 0; nt < 8; ++nt) {
            const int col = warp_n * 64 + nt * 8 + tig * 2;
            const float2 gv = *(const float2*)(gamma + col);
            const float2 bt = *(const float2*)(beta + col);
            const float2 lv = *(const float2*)(lw + col);
            #pragma unroll
            for (int mt = 0; mt < 2; ++mt) {
                #pragma unroll
                for (int h = 0; h < 2; ++h) {
                    float y0 = (c[mt][nt][2*h]   - mu_[mt][h]) * rs_[mt][h] * gv.x + bt.x;
                    float y1 = (c[mt][nt][2*h+1] - mu_[mt][h]) * rs_[mt][h] * gv.y + bt.y;
                    d_[mt][h] = fmaf(y0, lv.x, fmaf(y1, lv.y, d_[mt][h]));
                }
            }
        }
        #pragma unroll
        for (int off = 1; off <= 2; off <<= 1)
            #pragma unroll
            for (int mt = 0; mt < 2; ++mt)
                #pragma unroll
                for (int h = 0; h < 2; ++h)
                    d_[mt][h] += __shfl_xor_sync(0xffffffffu, d_[mt][h], off);
        if (tig == 0) {
            #pragma unroll
            for (int mt = 0; mt < 2; ++mt)
                #pragma unroll
                for (int h = 0; h < 2; ++h) {
                    int row = warp_m * 32 + mt * 16 + g + h * 8;
                    red[512 + warp_n * 64 + row] = d_[mt][h];
                }
        }
        __syncthreads();
        if (tid < 64) {
            float dt = red[512 + tid] + red[576 + tid] + red[640 + tid] + red[704 + tid]
                     + lb[0];
            int m = m0 + tid;
            out_ld[m] = mask[m] ? 0.f : dt;
        }
    }
}

// ---------------- launcher ---------------------------------------------------
extern "C" void kernel_launch(void* const* d_in, const int* in_sizes, int n_in,
                              void* d_out, int out_size) {
    const float*         x        = (const float*)d_in[0];
    const unsigned char* mask     = (const unsigned char*)d_in[1];
    const int*           duration = (const int*)d_in[2];

    int w = 3;
    if (n_in >= 14 && in_sizes[3] < 16) w = 4;
    const float* c1w = (const float*)d_in[w + 0];
    const float* c1b = (const float*)d_in[w + 1];
    const float* l1g = (const float*)d_in[w + 2];
    const float* l1b = (const float*)d_in[w + 3];
    const float* c2w = (const float*)d_in[w + 4];
    const float* c2b = (const float*)d_in[w + 5];
    const float* l2g = (const float*)d_in[w + 6];
    const float* l2b = (const float*)d_in[w + 7];
    const float* lw  = (const float*)d_in[w + 8];
    const float* lb  = (const float*)d_in[w + 9];

    float* out = (float*)d_out;
    const long long n_out = (long long)BB * TT * DD;
    const long long n_ld  = (long long)BB * SS;
    int has_ld  = (out_size >= n_out + n_ld);
    int has_dur = (out_size >= n_out + 2 * n_ld);
    int has_mel = (out_size >= n_out + 2 * n_ld + BB);
    float* out_ld  = out + n_out;
    float* out_dur = out_ld + n_ld;
    float* out_mel = out_dur + n_ld;

    void* p;
    cudaGetSymbolAddress(&p, g_xh);  __half* xh  = (__half*)p;
    cudaGetSymbolAddress(&p, g_xl);  __half* xl  = (__half*)p;
    cudaGetSymbolAddress(&p, g_h1h); __half* h1h = (__half*)p;
    cudaGetSymbolAddress(&p, g_h1l); __half* h1l = (__half*)p;
    cudaGetSymbolAddress(&p, g_W1h); __half* W1h = (__half*)p;
    cudaGetSymbolAddress(&p, g_W2h); __half* W2h = (__half*)p;

    cumsum_kernel<<<BB, SS>>>(duration, out_dur, out_mel, has_dur, has_mel);

    if (has_ld) {
        split_x_kernel<<<(BB * SS * DD) / 256, 256>>>(x, xh, xl);
        split_w_kernel<<<FF, 256>>>(c1w, W1h);
        split_w_kernel<<<FF, 256>>>(c2w, W2h);

        cudaFuncSetAttribute(mma_conv_ln_kernel<1>,
                             cudaFuncAttributeMaxDynamicSharedMemorySize, 49152);
        cudaFuncSetAttribute(mma_conv_ln_kernel<2>,
                             cudaFuncAttributeMaxDynamicSharedMemorySize, 49152);

        mma_conv_ln_kernel<1><<<BB * SS / 64, 256, 49152>>>(
            xh, xl, W1h, c1b, l1g, l1b, nullptr, nullptr, nullptr,
            h1h, h1l, nullptr);
        mma_conv_ln_kernel<2><<<BB * SS / 64, 256, 49152>>>(
            h1h, h1l, W2h, c2b, l2g, l2b, lw, lb, mask,
            nullptr, nullptr, out_ld);
    }

    gather_kernel<<<dim3(TT / 4, BB), 256>>>(x, out);
}

// round 6
// speedup vs baseline: 3.1516x; 1.2855x over previous
#include <cuda_runtime.h>
#include <cuda_fp16.h>
#include <stdint.h>

// ---------------- problem constants ----------------
#define BB 32
#define SS 1024
#define DD 256
#define FF 256
#define TT 8192
#define KDIM 768
#define NT 12          // K tiles of 64
#define GEMM_BLOCKS 512
#define GATHER_PER_GEMM 256

// ---------------- scratch (device globals; no allocation allowed) ----------
__device__ __half g_xh[(size_t)BB * SS * DD];
__device__ __half g_xl[(size_t)BB * SS * DD];
__device__ __half g_h1h[(size_t)BB * SS * FF];
__device__ __half g_h1l[(size_t)BB * SS * FF];
__device__ __half g_W1h[FF * KDIM];
__device__ __half g_W2h[FF * KDIM];
__device__ int g_cum[BB * SS];
__device__ int g_mellen[BB];

// ---------------- small helpers ----------------------------------------------
__device__ __forceinline__ uint32_t smem_u32(const void* p) {
    uint32_t a;
    asm("{ .reg .u64 t; cvta.to.shared.u64 t, %1; cvt.u32.u64 %0, t; }" : "=r"(a) : "l"(p));
    return a;
}
__device__ __forceinline__ void split_fp16(float v, __half& h, __half& l) {
    h = __float2half_rn(v);
    l = __float2half_rn(v - __half2float(h));
}
__device__ __forceinline__ void ldsm4(uint32_t r[4], uint32_t addr) {
    asm volatile("ldmatrix.sync.aligned.m8n8.x4.shared.b16 {%0,%1,%2,%3}, [%4];"
                 : "=r"(r[0]), "=r"(r[1]), "=r"(r[2]), "=r"(r[3]) : "r"(addr));
}
__device__ __forceinline__ void mma16816(float c[4], const uint32_t a[4],
                                         uint32_t b0, uint32_t b1) {
    asm volatile(
        "mma.sync.aligned.m16n8k16.row.col.f32.f16.f16.f32 "
        "{%0,%1,%2,%3}, {%4,%5,%6,%7}, {%8,%9}, {%0,%1,%2,%3};"
        : "+f"(c[0]), "+f"(c[1]), "+f"(c[2]), "+f"(c[3])
        : "r"(a[0]), "r"(a[1]), "r"(a[2]), "r"(a[3]), "r"(b0), "r"(b1));
}
__device__ __forceinline__ void cp16(uint32_t dst, const void* src, uint32_t sz) {
    asm volatile("cp.async.cg.shared.global [%0], [%1], 16, %2;"
                 :: "r"(dst), "l"(src), "r"(sz) : "memory");
}
#define CP_COMMIT() asm volatile("cp.async.commit_group;" ::: "memory")
#define CP_WAIT0()  asm volatile("cp.async.wait_group 0;" ::: "memory")

// swizzled byte offset of 16B chunk (row, kb 0..7) inside a [rows x 128B] tile
__device__ __forceinline__ uint32_t chunk_off64(int row, int kb) {
    return (uint32_t)(row * 128 + ((kb ^ (row & 7)) << 4));
}

// ---------------- fp32 -> fp16 (hi,lo) packers ------------------------------
__global__ void split_x_kernel(const float* __restrict__ x,
                               __half* __restrict__ xh, __half* __restrict__ xl) {
    int i = blockIdx.x * 256 + threadIdx.x;
    __half h, l;
    split_fp16(x[i], h, l);
    xh[i] = h;
    xl[i] = l;
}
// w[o][i][k] -> Wh[n=o][kk = k*256 + i]  (hi only)
__global__ void split_w_kernel(const float* __restrict__ w, __half* __restrict__ wh) {
    int n = blockIdx.x;
    int i = threadIdx.x;
    #pragma unroll
    for (int tap = 0; tap < 3; ++tap) {
        float v = w[(size_t)n * KDIM + i * 3 + tap];
        wh[(size_t)n * KDIM + tap * 256 + i] = __float2half_rn(v);
    }
}

// ---------------- per-batch inclusive cumsum of durations -------------------
__global__ void cumsum_kernel(const int* __restrict__ dur,
                              float* __restrict__ out_dur, float* __restrict__ out_mel,
                              int write_dur, int write_mel) {
    __shared__ int sdata[SS];
    int b = blockIdx.x;
    int t = threadIdx.x;
    int v = dur[b * SS + t];
    sdata[t] = v;
    __syncthreads();
    #pragma unroll
    for (int off = 1; off < SS; off <<= 1) {
        int add = (t >= off) ? sdata[t - off] : 0;
        __syncthreads();
        sdata[t] += add;
        __syncthreads();
    }
    g_cum[b * SS + t] = sdata[t];
    if (t == SS - 1) {
        int ml = min(sdata[t], TT);
        g_mellen[b] = ml;
        if (write_mel) out_mel[b] = (float)ml;
    }
    if (write_dur) out_dur[b * SS + t] = (float)v;
}

// ---------------- gather work routine (used by fused blocks + fallback) -----
// One gid handles 512 output rows of one batch. 256 threads: 32 rows/pass
// (8 lanes x float4 = 128B per row-segment), 16 passes.
__device__ __forceinline__ void gather_work(int gid, const float* __restrict__ x,
                                            float* __restrict__ out) {
    const int tid  = threadIdx.x;
    const int b    = gid >> 4;
    const int t0   = (gid & 15) << 9;
    const int* cum = g_cum + b * SS;
    const int ml   = g_mellen[b];
    const float4* xb = (const float4*)(x + (size_t)b * SS * DD);
    float4* ob = (float4*)(out + (size_t)b * TT * DD);
    const int rsub = tid >> 3;
    const int csub = tid & 7;
    for (int pass = 0; pass < 16; ++pass) {
        int t = t0 + pass * 32 + rsub;
        float4* orow = ob + (size_t)t * 64;
        if (t < ml) {
            int lo = 0, hi = SS;
            while (lo < hi) {
                int mid = (lo + hi) >> 1;
                if (cum[mid] > t) hi = mid; else lo = mid + 1;
            }
            int src = min(lo, SS - 1);
            const float4* xr = xb + (size_t)src * 64;
            #pragma unroll
            for (int c8 = 0; c8 < 8; ++c8)
                orow[c8 * 8 + csub] = xr[c8 * 8 + csub];
        } else {
            float4 z = make_float4(0.f, 0.f, 0.f, 0.f);
            #pragma unroll
            for (int c8 = 0; c8 < 8; ++c8)
                orow[c8 * 8 + csub] = z;
        }
    }
}

__global__ void gather_kernel(const float* __restrict__ x, float* __restrict__ out) {
    gather_work(blockIdx.x, x, out);
}

// ---------------- split-fp16 conv-GEMM, full-N tile, fused LN epilogue ------
// CTA 64(M) x 256(N=full F), BK=64, 8 warps (2m x 4n), warp tile 32x64.
// 2-term: C = Ah*Bh + Al*Bh.
// smem/stage: Ah 8K | Al 8K | Bh 32K = 48KB, double buffered = 96KB.
// Blocks >= GEMM_BLOCKS run gather backfill work instead.
template<int MODE>
__global__ __launch_bounds__(256, 2) void mma_conv_ln_kernel(
    const __half* __restrict__ Ah_g, const __half* __restrict__ Al_g,
    const __half* __restrict__ Wh_g,
    const float* __restrict__ bias,
    const float* __restrict__ gamma, const float* __restrict__ beta,
    const float* __restrict__ lw, const float* __restrict__ lb,
    const unsigned char* __restrict__ mask,
    __half* __restrict__ oh, __half* __restrict__ ol,
    float* __restrict__ out_ld,
    const float* __restrict__ xg, float* __restrict__ outg, int gid_base)
{
    if (blockIdx.x >= GEMM_BLOCKS) {
        gather_work((int)blockIdx.x - GEMM_BLOCKS + gid_base, xg, outg);
        return;
    }

    extern __shared__ char smem[];
    const uint32_t sb = smem_u32(smem);
    const int tid  = threadIdx.x;
    const int wid  = tid >> 5;
    const int lane = tid & 31;
    const int m0     = blockIdx.x * 64;
    const int batch  = m0 >> 10;
    const int s_base = m0 & (SS - 1);
    const int warp_m = wid & 1;       // 0..1, 32 rows each
    const int warp_n = wid >> 1;      // 0..3, 64 cols each

    // cp.async chunk constants
    const int rowA0 = tid >> 3, kbA0 = (tid & 7);            // A chunk id = tid
    const int rowA1 = (tid + 256) >> 3, kbA1 = tid & 7;      // A chunk id = tid+256
    const uint32_t dstA0 = chunk_off64(rowA0, kbA0);
    const uint32_t dstA1 = chunk_off64(rowA1, kbA1);
    const __half* Ah_b = Ah_g + ((size_t)batch << 10) * DD;
    const __half* Al_b = Al_g + ((size_t)batch << 10) * DD;

    uint32_t aoff[2][4], boff[4][4];
    #pragma unroll
    for (int mt = 0; mt < 2; ++mt) {
        int row = warp_m * 32 + mt * 16 + (lane & 15);
        #pragma unroll
        for (int ks = 0; ks < 4; ++ks)
            aoff[mt][ks] = chunk_off64(row, ks * 2 + (lane >> 4));
    }
    #pragma unroll
    for (int jp = 0; jp < 4; ++jp) {
        int row = warp_n * 64 + jp * 16 + ((lane >> 4) << 3) + (lane & 7);
        #pragma unroll
        for (int ks = 0; ks < 4; ++ks)
            boff[jp][ks] = 16384u + chunk_off64(row, ks * 2 + ((lane >> 3) & 1));
    }

    float c[2][8][4];
    #pragma unroll
    for (int mt = 0; mt < 2; ++mt)
        #pragma unroll
        for (int nt = 0; nt < 8; ++nt)
            #pragma unroll
            for (int q = 0; q < 4; ++q) c[mt][nt][q] = 0.f;

    auto issue = [&](int kt, int buf) {
        const int tap = kt >> 2;
        const int i0  = (kt & 3) * 64;
        const uint32_t stb = sb + (uint32_t)buf * 49152u;
        // A hi + lo (2 chunks each)
        {
            int sA = s_base + rowA0 + tap - 1;
            uint32_t szA = ((unsigned)sA < (unsigned)SS) ? 16u : 0u;
            int sAc = min(max(sA, 0), SS - 1);
            size_t ag = ((size_t)sAc * DD) + i0 + kbA0 * 8;
            cp16(stb + dstA0,         Ah_b + ag, szA);
            cp16(stb + 8192u + dstA0, Al_b + ag, szA);
        }
        {
            int sA = s_base + rowA1 + tap - 1;
            uint32_t szA = ((unsigned)sA < (unsigned)SS) ? 16u : 0u;
            int sAc = min(max(sA, 0), SS - 1);
            size_t ag = ((size_t)sAc * DD) + i0 + kbA1 * 8;
            cp16(stb + dstA1,         Ah_b + ag, szA);
            cp16(stb + 8192u + dstA1, Al_b + ag, szA);
        }
        // B: 8 chunks per thread
        #pragma unroll
        for (int j = 0; j < 8; ++j) {
            int id = tid + j * 256;
            int rowB = id >> 3, kbB = id & 7;
            size_t wg = (size_t)rowB * KDIM + kt * 64 + kbB * 8;
            cp16(stb + 16384u + chunk_off64(rowB, kbB), Wh_g + wg, 16u);
        }
    };

    issue(0, 0);
    CP_COMMIT();

    for (int kt = 0; kt < NT; ++kt) {
        CP_WAIT0();
        __syncthreads();
        if (kt + 1 < NT) issue(kt + 1, (kt + 1) & 1);
        CP_COMMIT();

        const uint32_t stb = sb + (uint32_t)(kt & 1) * 49152u;
        #pragma unroll
        for (int ks = 0; ks < 4; ++ks) {
            uint32_t ah[2][4], al[2][4];
            ldsm4(ah[0], stb + aoff[0][ks]);
            ldsm4(ah[1], stb + aoff[1][ks]);
            ldsm4(al[0], stb + 8192u + aoff[0][ks]);
            ldsm4(al[1], stb + 8192u + aoff[1][ks]);
            #pragma unroll
            for (int jp = 0; jp < 4; ++jp) {
                uint32_t bh[4];
                ldsm4(bh, stb + boff[jp][ks]);
                const int nA = 2 * jp, nB = 2 * jp + 1;
                mma16816(c[0][nA], ah[0], bh[0], bh[1]);
                mma16816(c[1][nA], ah[1], bh[0], bh[1]);
                mma16816(c[0][nB], ah[0], bh[2], bh[3]);
                mma16816(c[1][nB], ah[1], bh[2], bh[3]);
                mma16816(c[0][nA], al[0], bh[0], bh[1]);
                mma16816(c[1][nA], al[1], bh[0], bh[1]);
                mma16816(c[0][nB], al[0], bh[2], bh[3]);
                mma16816(c[1][nB], al[1], bh[2], bh[3]);
            }
        }
    }

    // =================== fused epilogue ===================
    const int g   = lane >> 2;
    const int tig = lane & 3;
    __syncthreads();                    // mainloop smem reads done; reuse smem
    float* red = (float*)smem;          // [0:256) sum, [256:512) sq, [512:768) dot

    float s_[2][2] = {{0.f, 0.f}, {0.f, 0.f}};
    float q_[2][2] = {{0.f, 0.f}, {0.f, 0.f}};
    #pragma unroll
    for (int nt = 0; nt < 8; ++nt) {
        const int col = warp_n * 64 + nt * 8 + tig * 2;
        const float2 bv = *(const float2*)(bias + col);
        #pragma unroll
        for (int mt = 0; mt < 2; ++mt) {
            float v0 = fmaxf(c[mt][nt][0] + bv.x, 0.f);
            float v1 = fmaxf(c[mt][nt][1] + bv.y, 0.f);
            float v2 = fmaxf(c[mt][nt][2] + bv.x, 0.f);
            float v3 = fmaxf(c[mt][nt][3] + bv.y, 0.f);
            c[mt][nt][0] = v0; c[mt][nt][1] = v1;
            c[mt][nt][2] = v2; c[mt][nt][3] = v3;
            s_[mt][0] += v0 + v1;           s_[mt][1] += v2 + v3;
            q_[mt][0] += v0 * v0 + v1 * v1; q_[mt][1] += v2 * v2 + v3 * v3;
        }
    }
    #pragma unroll
    for (int off = 1; off <= 2; off <<= 1) {
        #pragma unroll
        for (int mt = 0; mt < 2; ++mt)
            #pragma unroll
            for (int h = 0; h < 2; ++h) {
                s_[mt][h] += __shfl_xor_sync(0xffffffffu, s_[mt][h], off);
                q_[mt][h] += __shfl_xor_sync(0xffffffffu, q_[mt][h], off);
            }
    }
    if (tig == 0) {
        #pragma unroll
        for (int mt = 0; mt < 2; ++mt)
            #pragma unroll
            for (int h = 0; h < 2; ++h) {
                int row = warp_m * 32 + mt * 16 + g + h * 8;
                red[warp_n * 64 + row]        = s_[mt][h];
                red[256 + warp_n * 64 + row]  = q_[mt][h];
            }
    }
    __syncthreads();
    float mu_[2][2], rs_[2][2];
    #pragma unroll
    for (int mt = 0; mt < 2; ++mt)
        #pragma unroll
        for (int h = 0; h < 2; ++h) {
            int row = warp_m * 32 + mt * 16 + g + h * 8;
            float st = red[row] + red[64 + row] + red[128 + row] + red[192 + row];
            float qt = red[256 + row] + red[320 + row] + red[384 + row] + red[448 + row];
            float mu  = st * (1.f / 256.f);
            float var = fmaxf(qt * (1.f / 256.f) - mu * mu, 0.f);
            mu_[mt][h] = mu;
            rs_[mt][h] = rsqrtf(var + 1e-5f);
        }

    if (MODE == 1) {
        #pragma unroll
        for (int nt = 0; nt < 8; ++nt) {
            const int col = warp_n * 64 + nt * 8 + tig * 2;
            const float2 gv = *(const float2*)(gamma + col);
            const float2 bt = *(const float2*)(beta + col);
            #pragma unroll
            for (int mt = 0; mt < 2; ++mt) {
                #pragma unroll
                for (int h = 0; h < 2; ++h) {
                    int row = warp_m * 32 + mt * 16 + g + h * 8;
                    float y0 = (c[mt][nt][2*h]   - mu_[mt][h]) * rs_[mt][h] * gv.x + bt.x;
                    float y1 = (c[mt][nt][2*h+1] - mu_[mt][h]) * rs_[mt][h] * gv.y + bt.y;
                    __half h0, l0, h1, l1;
                    split_fp16(y0, h0, l0);
                    split_fp16(y1, h1, l1);
                    size_t base = (size_t)(m0 + row) * FF + col;
                    *(__half2*)(oh + base) = __halves2half2(h0, h1);
                    *(__half2*)(ol + base) = __halves2half2(l0, l1);
                }
            }
        }
    } else {
        float d_[2][2] = {{0.f, 0.f}, {0.f, 0.f}};
        #pragma unroll
        for (int nt = 0; nt < 8; ++nt) {
            const int col = warp_n * 64 + nt * 8 + tig * 2;
            const float2 gv = *(const float2*)(gamma + col);
            const float2 bt = *(const float2*)(beta + col);
            const float2 lv = *(const float2*)(lw + col);
            #pragma unroll
            for (int mt = 0; mt < 2; ++mt) {
                #pragma unroll
                for (int h = 0; h < 2; ++h) {
                    float y0 = (c[mt][nt][2*h]   - mu_[mt][h]) * rs_[mt][h] * gv.x + bt.x;
                    float y1 = (c[mt][nt][2*h+1] - mu_[mt][h]) * rs_[mt][h] * gv.y + bt.y;
                    d_[mt][h] = fmaf(y0, lv.x, fmaf(y1, lv.y, d_[mt][h]));
                }
            }
        }
        #pragma unroll
        for (int off = 1; off <= 2; off <<= 1)
            #pragma unroll
            for (int mt = 0; mt < 2; ++mt)
                #pragma unroll
                for (int h = 0; h < 2; ++h)
                    d_[mt][h] += __shfl_xor_sync(0xffffffffu, d_[mt][h], off);
        if (tig == 0) {
            #pragma unroll
            for (int mt = 0; mt < 2; ++mt)
                #pragma unroll
                for (int h = 0; h < 2; ++h) {
                    int row = warp_m * 32 + mt * 16 + g + h * 8;
                    red[512 + warp_n * 64 + row] = d_[mt][h];
                }
        }
        __syncthreads();
        if (tid < 64) {
            float dt = red[512 + tid] + red[576 + tid] + red[640 + tid] + red[704 + tid]
                     + lb[0];
            int m = m0 + tid;
            out_ld[m] = mask[m] ? 0.f : dt;
        }
    }
}

// ---------------- launcher ---------------------------------------------------
extern "C" void kernel_launch(void* const* d_in, const int* in_sizes, int n_in,
                              void* d_out, int out_size) {
    const float*         x        = (const float*)d_in[0];
    const unsigned char* mask     = (const unsigned char*)d_in[1];
    const int*           duration = (const int*)d_in[2];

    int w = 3;
    if (n_in >= 14 && in_sizes[3] < 16) w = 4;
    const float* c1w = (const float*)d_in[w + 0];
    const float* c1b = (const float*)d_in[w + 1];
    const float* l1g = (const float*)d_in[w + 2];
    const float* l1b = (const float*)d_in[w + 3];
    const float* c2w = (const float*)d_in[w + 4];
    const float* c2b = (const float*)d_in[w + 5];
    const float* l2g = (const float*)d_in[w + 6];
    const float* l2b = (const float*)d_in[w + 7];
    const float* lw  = (const float*)d_in[w + 8];
    const float* lb  = (const float*)d_in[w + 9];

    float* out = (float*)d_out;
    const long long n_out = (long long)BB * TT * DD;
    const long long n_ld  = (long long)BB * SS;
    int has_ld  = (out_size >= n_out + n_ld);
    int has_dur = (out_size >= n_out + 2 * n_ld);
    int has_mel = (out_size >= n_out + 2 * n_ld + BB);
    float* out_ld  = out + n_out;
    float* out_dur = out_ld + n_ld;
    float* out_mel = out_dur + n_ld;

    void* p;
    cudaGetSymbolAddress(&p, g_xh);  __half* xh  = (__half*)p;
    cudaGetSymbolAddress(&p, g_xl);  __half* xl  = (__half*)p;
    cudaGetSymbolAddress(&p, g_h1h); __half* h1h = (__half*)p;
    cudaGetSymbolAddress(&p, g_h1l); __half* h1l = (__half*)p;
    cudaGetSymbolAddress(&p, g_W1h); __half* W1h = (__half*)p;
    cudaGetSymbolAddress(&p, g_W2h); __half* W2h = (__half*)p;

    cumsum_kernel<<<BB, SS>>>(duration, out_dur, out_mel, has_dur, has_mel);

    if (has_ld) {
        split_x_kernel<<<(BB * SS * DD) / 256, 256>>>(x, xh, xl);
        split_w_kernel<<<FF, 256>>>(c1w, W1h);
        split_w_kernel<<<FF, 256>>>(c2w, W2h);

        cudaFuncSetAttribute(mma_conv_ln_kernel<1>,
                             cudaFuncAttributeMaxDynamicSharedMemorySize, 98304);
        cudaFuncSetAttribute(mma_conv_ln_kernel<2>,
                             cudaFuncAttributeMaxDynamicSharedMemorySize, 98304);

        mma_conv_ln_kernel<1><<<GEMM_BLOCKS + GATHER_PER_GEMM, 256, 98304>>>(
            xh, xl, W1h, c1b, l1g, l1b, nullptr, nullptr, nullptr,
            h1h, h1l, nullptr, x, out, 0);
        mma_conv_ln_kernel<2><<<GEMM_BLOCKS + GATHER_PER_GEMM, 256, 98304>>>(
            h1h, h1l, W2h, c2b, l2g, l2b, lw, lb, mask,
            nullptr, nullptr, out_ld, x, out, GATHER_PER_GEMM);
    } else {
        gather_kernel<<<BB * 16, 256>>>(x, out);
    }
}

// round 7
// speedup vs baseline: 4.4145x; 1.4007x over previous
#include <cuda_runtime.h>
#include <cuda_fp16.h>
#include <stdint.h>

// ---------------- problem constants ----------------
#define BB 32
#define SS 1024
#define DD 256
#define FF 256
#define TT 8192
#define KDIM 768
#define NT 12          // K tiles of 64
#define GEMM_BLOCKS 512
#define GATHER_PER_GEMM 256

// ---------------- scratch (device globals; no allocation allowed) ----------
__device__ __half g_xh[(size_t)BB * SS * DD];
__device__ __half g_h1h[(size_t)BB * SS * FF];
__device__ __half g_W1h[FF * KDIM];
__device__ __half g_W2h[FF * KDIM];
__device__ int g_cum[BB * SS];
__device__ int g_mellen[BB];

// ---------------- small helpers ----------------------------------------------
__device__ __forceinline__ uint32_t smem_u32(const void* p) {
    uint32_t a;
    asm("{ .reg .u64 t; cvta.to.shared.u64 t, %1; cvt.u32.u64 %0, t; }" : "=r"(a) : "l"(p));
    return a;
}
__device__ __forceinline__ void ldsm4(uint32_t r[4], uint32_t addr) {
    asm volatile("ldmatrix.sync.aligned.m8n8.x4.shared.b16 {%0,%1,%2,%3}, [%4];"
                 : "=r"(r[0]), "=r"(r[1]), "=r"(r[2]), "=r"(r[3]) : "r"(addr));
}
__device__ __forceinline__ void mma16816(float c[4], const uint32_t a[4],
                                         uint32_t b0, uint32_t b1) {
    asm volatile(
        "mma.sync.aligned.m16n8k16.row.col.f32.f16.f16.f32 "
        "{%0,%1,%2,%3}, {%4,%5,%6,%7}, {%8,%9}, {%0,%1,%2,%3};"
        : "+f"(c[0]), "+f"(c[1]), "+f"(c[2]), "+f"(c[3])
        : "r"(a[0]), "r"(a[1]), "r"(a[2]), "r"(a[3]), "r"(b0), "r"(b1));
}
__device__ __forceinline__ void cp16(uint32_t dst, const void* src, uint32_t sz) {
    asm volatile("cp.async.cg.shared.global [%0], [%1], 16, %2;"
                 :: "r"(dst), "l"(src), "r"(sz) : "memory");
}
#define CP_COMMIT() asm volatile("cp.async.commit_group;" ::: "memory")
#define CP_WAIT0()  asm volatile("cp.async.wait_group 0;" ::: "memory")

// swizzled byte offset of 16B chunk (row, kb 0..7) inside a [rows x 128B] tile
__device__ __forceinline__ uint32_t chunk_off64(int row, int kb) {
    return (uint32_t)(row * 128 + ((kb ^ (row & 7)) << 4));
}

// ---------------- fused prep kernel ------------------------------------------
// blocks [0,32): per-batch cumsum of durations (+optional dur/mel outputs)
// blocks [32, 32+2048): x -> fp16 (4096 elems per block)
// blocks [2080, 2144): conv1 weight transpose+round
// blocks [2144, 2208): conv2 weight transpose+round
#define PREP_X_BLOCKS   2048
#define PREP_W_BLOCKS   64
#define PREP_GRID       (32 + PREP_X_BLOCKS + 2 * PREP_W_BLOCKS)

__global__ __launch_bounds__(1024) void prep_kernel(
    const float* __restrict__ x, const int* __restrict__ dur,
    const float* __restrict__ w1, const float* __restrict__ w2,
    __half* __restrict__ xh, __half* __restrict__ wh1, __half* __restrict__ wh2,
    float* __restrict__ out_dur, float* __restrict__ out_mel,
    int write_dur, int write_mel)
{
    const int bid = blockIdx.x;
    const int tid = threadIdx.x;

    if (bid < 32) {
        // ---- cumsum for batch bid ----
        __shared__ int sdata[SS];
        int b = bid;
        int v = dur[b * SS + tid];
        sdata[tid] = v;
        __syncthreads();
        #pragma unroll
        for (int off = 1; off < SS; off <<= 1) {
            int add = (tid >= off) ? sdata[tid - off] : 0;
            __syncthreads();
            sdata[tid] += add;
            __syncthreads();
        }
        g_cum[b * SS + tid] = sdata[tid];
        if (tid == SS - 1) {
            int ml = min(sdata[tid], TT);
            g_mellen[b] = ml;
            if (write_mel) out_mel[b] = (float)ml;
        }
        if (write_dur) out_dur[b * SS + tid] = (float)v;
    } else if (bid < 32 + PREP_X_BLOCKS) {
        // ---- x -> fp16 ----
        size_t base = (size_t)(bid - 32) * 4096 + tid;
        const float4* xin = (const float4*)x;
        // 4 elems per thread, vectorized: read float4, write half2 pairs
        float4 v = xin[base >> 2 << 0]; // placeholder to keep alignment simple
        // simpler scalar-x4 path:
        size_t i0 = (size_t)(bid - 32) * 4096;
        #pragma unroll
        for (int j = 0; j < 4; ++j) {
            size_t i = i0 + tid + j * 1024;
            xh[i] = __float2half_rn(x[i]);
        }
        (void)v;
    } else {
        // ---- weight transpose: w[o][i][k] -> Wh[o][k*256+i] ----
        const float* w  = (bid < 32 + PREP_X_BLOCKS + PREP_W_BLOCKS) ? w1 : w2;
        __half* wh      = (bid < 32 + PREP_X_BLOCKS + PREP_W_BLOCKS) ? wh1 : wh2;
        int lb = (bid < 32 + PREP_X_BLOCKS + PREP_W_BLOCKS)
                   ? (bid - 32 - PREP_X_BLOCKS) : (bid - 32 - PREP_X_BLOCKS - PREP_W_BLOCKS);
        int idx = lb * 1024 + tid;          // over FF*DD = 65536
        int n = idx >> 8;
        int i = idx & 255;
        #pragma unroll
        for (int tap = 0; tap < 3; ++tap) {
            float v = w[(size_t)n * KDIM + i * 3 + tap];
            wh[(size_t)n * KDIM + tap * 256 + i] = __float2half_rn(v);
        }
    }
}

// ---------------- gather work routine (used by fused blocks + fallback) -----
__device__ __forceinline__ void gather_work(int gid, const float* __restrict__ x,
                                            float* __restrict__ out) {
    const int tid  = threadIdx.x;
    const int b    = gid >> 4;
    const int t0   = (gid & 15) << 9;
    const int* cum = g_cum + b * SS;
    const int ml   = g_mellen[b];
    const float4* xb = (const float4*)(x + (size_t)b * SS * DD);
    float4* ob = (float4*)(out + (size_t)b * TT * DD);
    const int rsub = tid >> 3;
    const int csub = tid & 7;
    for (int pass = 0; pass < 16; ++pass) {
        int t = t0 + pass * 32 + rsub;
        float4* orow = ob + (size_t)t * 64;
        if (t < ml) {
            int lo = 0, hi = SS;
            while (lo < hi) {
                int mid = (lo + hi) >> 1;
                if (cum[mid] > t) hi = mid; else lo = mid + 1;
            }
            int src = min(lo, SS - 1);
            const float4* xr = xb + (size_t)src * 64;
            #pragma unroll
            for (int c8 = 0; c8 < 8; ++c8)
                orow[c8 * 8 + csub] = xr[c8 * 8 + csub];
        } else {
            float4 z = make_float4(0.f, 0.f, 0.f, 0.f);
            #pragma unroll
            for (int c8 = 0; c8 < 8; ++c8)
                orow[c8 * 8 + csub] = z;
        }
    }
}

__global__ void gather_kernel(const float* __restrict__ x, float* __restrict__ out) {
    gather_work(blockIdx.x, x, out);
}

// ---------------- fp16 conv-GEMM, full-N tile, fused LN epilogue -------------
// CTA 64(M) x 256(N=full F), BK=64, 8 warps (2m x 4n), warp tile 32x64.
// smem/stage: A 8K | B 32K = 40KB, double buffered = 80KB.
// Blocks >= GEMM_BLOCKS run gather backfill work instead.
template<int MODE>  // 1: LN -> fp16 out; 2: LN -> linear head -> log_dur
__global__ __launch_bounds__(256, 2) void mma_conv_ln_kernel(
    const __half* __restrict__ A_g, const __half* __restrict__ W_g,
    const float* __restrict__ bias,
    const float* __restrict__ gamma, const float* __restrict__ beta,
    const float* __restrict__ lw, const float* __restrict__ lb,
    const unsigned char* __restrict__ mask,
    __half* __restrict__ oh, float* __restrict__ out_ld,
    const float* __restrict__ xg, float* __restrict__ outg, int gid_base)
{
    if (blockIdx.x >= GEMM_BLOCKS) {
        gather_work((int)blockIdx.x - GEMM_BLOCKS + gid_base, xg, outg);
        return;
    }

    extern __shared__ char smem[];
    const uint32_t sb = smem_u32(smem);
    const int tid  = threadIdx.x;
    const int wid  = tid >> 5;
    const int lane = tid & 31;
    const int m0     = blockIdx.x * 64;
    const int batch  = m0 >> 10;
    const int s_base = m0 & (SS - 1);
    const int warp_m = wid & 1;       // 0..1, 32 rows each
    const int warp_n = wid >> 1;      // 0..3, 64 cols each

    const int rowA0 = tid >> 3, kbA0 = tid & 7;
    const int rowA1 = (tid + 256) >> 3, kbA1 = tid & 7;
    const uint32_t dstA0 = chunk_off64(rowA0, kbA0);
    const uint32_t dstA1 = chunk_off64(rowA1, kbA1);
    const __half* A_b = A_g + ((size_t)batch << 10) * DD;

    uint32_t aoff[2][4], boff[4][4];
    #pragma unroll
    for (int mt = 0; mt < 2; ++mt) {
        int row = warp_m * 32 + mt * 16 + (lane & 15);
        #pragma unroll
        for (int ks = 0; ks < 4; ++ks)
            aoff[mt][ks] = chunk_off64(row, ks * 2 + (lane >> 4));
    }
    #pragma unroll
    for (int jp = 0; jp < 4; ++jp) {
        int row = warp_n * 64 + jp * 16 + ((lane >> 4) << 3) + (lane & 7);
        #pragma unroll
        for (int ks = 0; ks < 4; ++ks)
            boff[jp][ks] = 8192u + chunk_off64(row, ks * 2 + ((lane >> 3) & 1));
    }

    float c[2][8][4];
    #pragma unroll
    for (int mt = 0; mt < 2; ++mt)
        #pragma unroll
        for (int nt = 0; nt < 8; ++nt)
            #pragma unroll
            for (int q = 0; q < 4; ++q) c[mt][nt][q] = 0.f;

    auto issue = [&](int kt, int buf) {
        const int tap = kt >> 2;
        const int i0  = (kt & 3) * 64;
        const uint32_t stb = sb + (uint32_t)buf * 40960u;
        {
            int sA = s_base + rowA0 + tap - 1;
            uint32_t szA = ((unsigned)sA < (unsigned)SS) ? 16u : 0u;
            int sAc = min(max(sA, 0), SS - 1);
            cp16(stb + dstA0, A_b + (size_t)sAc * DD + i0 + kbA0 * 8, szA);
        }
        {
            int sA = s_base + rowA1 + tap - 1;
            uint32_t szA = ((unsigned)sA < (unsigned)SS) ? 16u : 0u;
            int sAc = min(max(sA, 0), SS - 1);
            cp16(stb + dstA1, A_b + (size_t)sAc * DD + i0 + kbA1 * 8, szA);
        }
        #pragma unroll
        for (int j = 0; j < 8; ++j) {
            int id = tid + j * 256;
            int rowB = id >> 3, kbB = id & 7;
            size_t wg = (size_t)rowB * KDIM + kt * 64 + kbB * 8;
            cp16(stb + 8192u + chunk_off64(rowB, kbB), W_g + wg, 16u);
        }
    };

    issue(0, 0);
    CP_COMMIT();

    for (int kt = 0; kt < NT; ++kt) {
        CP_WAIT0();
        __syncthreads();
        if (kt + 1 < NT) issue(kt + 1, (kt + 1) & 1);
        CP_COMMIT();

        const uint32_t stb = sb + (uint32_t)(kt & 1) * 40960u;
        #pragma unroll
        for (int ks = 0; ks < 4; ++ks) {
            uint32_t ah[2][4];
            ldsm4(ah[0], stb + aoff[0][ks]);
            ldsm4(ah[1], stb + aoff[1][ks]);
            #pragma unroll
            for (int jp = 0; jp < 4; ++jp) {
                uint32_t bh[4];
                ldsm4(bh, stb + boff[jp][ks]);
                const int nA = 2 * jp, nB = 2 * jp + 1;
                mma16816(c[0][nA], ah[0], bh[0], bh[1]);
                mma16816(c[1][nA], ah[1], bh[0], bh[1]);
                mma16816(c[0][nB], ah[0], bh[2], bh[3]);
                mma16816(c[1][nB], ah[1], bh[2], bh[3]);
            }
        }
    }

    // =================== fused epilogue ===================
    const int g   = lane >> 2;
    const int tig = lane & 3;
    __syncthreads();
    float* red = (float*)smem;          // [0:256) sum, [256:512) sq, [512:768) dot

    float s_[2][2] = {{0.f, 0.f}, {0.f, 0.f}};
    float q_[2][2] = {{0.f, 0.f}, {0.f, 0.f}};
    #pragma unroll
    for (int nt = 0; nt < 8; ++nt) {
        const int col = warp_n * 64 + nt * 8 + tig * 2;
        const float2 bv = *(const float2*)(bias + col);
        #pragma unroll
        for (int mt = 0; mt < 2; ++mt) {
            float v0 = fmaxf(c[mt][nt][0] + bv.x, 0.f);
            float v1 = fmaxf(c[mt][nt][1] + bv.y, 0.f);
            float v2 = fmaxf(c[mt][nt][2] + bv.x, 0.f);
            float v3 = fmaxf(c[mt][nt][3] + bv.y, 0.f);
            c[mt][nt][0] = v0; c[mt][nt][1] = v1;
            c[mt][nt][2] = v2; c[mt][nt][3] = v3;
            s_[mt][0] += v0 + v1;           s_[mt][1] += v2 + v3;
            q_[mt][0] += v0 * v0 + v1 * v1; q_[mt][1] += v2 * v2 + v3 * v3;
        }
    }
    #pragma unroll
    for (int off = 1; off <= 2; off <<= 1) {
        #pragma unroll
        for (int mt = 0; mt < 2; ++mt)
            #pragma unroll
            for (int h = 0; h < 2; ++h) {
                s_[mt][h] += __shfl_xor_sync(0xffffffffu, s_[mt][h], off);
                q_[mt][h] += __shfl_xor_sync(0xffffffffu, q_[mt][h], off);
            }
    }
    if (tig == 0) {
        #pragma unroll
        for (int mt = 0; mt < 2; ++mt)
            #pragma unroll
            for (int h = 0; h < 2; ++h) {
                int row = warp_m * 32 + mt * 16 + g + h * 8;
                red[warp_n * 64 + row]        = s_[mt][h];
                red[256 + warp_n * 64 + row]  = q_[mt][h];
            }
    }
    __syncthreads();
    float mu_[2][2], rs_[2][2];
    #pragma unroll
    for (int mt = 0; mt < 2; ++mt)
        #pragma unroll
        for (int h = 0; h < 2; ++h) {
            int row = warp_m * 32 + mt * 16 + g + h * 8;
            float st = red[row] + red[64 + row] + red[128 + row] + red[192 + row];
            float qt = red[256 + row] + red[320 + row] + red[384 + row] + red[448 + row];
            float mu  = st * (1.f / 256.f);
            float var = fmaxf(qt * (1.f / 256.f) - mu * mu, 0.f);
            mu_[mt][h] = mu;
            rs_[mt][h] = rsqrtf(var + 1e-5f);
        }

    if (MODE == 1) {
        #pragma unroll
        for (int nt = 0; nt < 8; ++nt) {
            const int col = warp_n * 64 + nt * 8 + tig * 2;
            const float2 gv = *(const float2*)(gamma + col);
            const float2 bt = *(const float2*)(beta + col);
            #pragma unroll
            for (int mt = 0; mt < 2; ++mt) {
                #pragma unroll
                for (int h = 0; h < 2; ++h) {
                    int row = warp_m * 32 + mt * 16 + g + h * 8;
                    float y0 = (c[mt][nt][2*h]   - mu_[mt][h]) * rs_[mt][h] * gv.x + bt.x;
                    float y1 = (c[mt][nt][2*h+1] - mu_[mt][h]) * rs_[mt][h] * gv.y + bt.y;
                    *(__half2*)(oh + (size_t)(m0 + row) * FF + col) =
                        __halves2half2(__float2half_rn(y0), __float2half_rn(y1));
                }
            }
        }
    } else {
        float d_[2][2] = {{0.f, 0.f}, {0.f, 0.f}};
        #pragma unroll
        for (int nt = 0; nt < 8; ++nt) {
            const int col = warp_n * 64 + nt * 8 + tig * 2;
            const float2 gv = *(const float2*)(gamma + col);
            const float2 bt = *(const float2*)(beta + col);
            const float2 lv = *(const float2*)(lw + col);
            #pragma unroll
            for (int mt = 0; mt < 2; ++mt) {
                #pragma unroll
                for (int h = 0; h < 2; ++h) {
                    float y0 = (c[mt][nt][2*h]   - mu_[mt][h]) * rs_[mt][h] * gv.x + bt.x;
                    float y1 = (c[mt][nt][2*h+1] - mu_[mt][h]) * rs_[mt][h] * gv.y + bt.y;
                    d_[mt][h] = fmaf(y0, lv.x, fmaf(y1, lv.y, d_[mt][h]));
                }
            }
        }
        #pragma unroll
        for (int off = 1; off <= 2; off <<= 1)
            #pragma unroll
            for (int mt = 0; mt < 2; ++mt)
                #pragma unroll
                for (int h = 0; h < 2; ++h)
                    d_[mt][h] += __shfl_xor_sync(0xffffffffu, d_[mt][h], off);
        if (tig == 0) {
            #pragma unroll
            for (int mt = 0; mt < 2; ++mt)
                #pragma unroll
                for (int h = 0; h < 2; ++h) {
                    int row = warp_m * 32 + mt * 16 + g + h * 8;
                    red[512 + warp_n * 64 + row] = d_[mt][h];
                }
        }
        __syncthreads();
        if (tid < 64) {
            float dt = red[512 + tid] + red[576 + tid] + red[640 + tid] + red[704 + tid]
                     + lb[0];
            int m = m0 + tid;
            out_ld[m] = mask[m] ? 0.f : dt;
        }
    }
}

// ---------------- launcher ---------------------------------------------------
extern "C" void kernel_launch(void* const* d_in, const int* in_sizes, int n_in,
                              void* d_out, int out_size) {
    const float*         x        = (const float*)d_in[0];
    const unsigned char* mask     = (const unsigned char*)d_in[1];
    const int*           duration = (const int*)d_in[2];

    int w = 3;
    if (n_in >= 14 && in_sizes[3] < 16) w = 4;
    const float* c1w = (const float*)d_in[w + 0];
    const float* c1b = (const float*)d_in[w + 1];
    const float* l1g = (const float*)d_in[w + 2];
    const float* l1b = (const float*)d_in[w + 3];
    const float* c2w = (const float*)d_in[w + 4];
    const float* c2b = (const float*)d_in[w + 5];
    const float* l2g = (const float*)d_in[w + 6];
    const float* l2b = (const float*)d_in[w + 7];
    const float* lw  = (const float*)d_in[w + 8];
    const float* lb  = (const float*)d_in[w + 9];

    float* out = (float*)d_out;
    const long long n_out = (long long)BB * TT * DD;
    const long long n_ld  = (long long)BB * SS;
    int has_ld  = (out_size >= n_out + n_ld);
    int has_dur = (out_size >= n_out + 2 * n_ld);
    int has_mel = (out_size >= n_out + 2 * n_ld + BB);
    float* out_ld  = out + n_out;
    float* out_dur = out_ld + n_ld;
    float* out_mel = out_dur + n_ld;

    void* p;
    cudaGetSymbolAddress(&p, g_xh);  __half* xh  = (__half*)p;
    cudaGetSymbolAddress(&p, g_h1h); __half* h1h = (__half*)p;
    cudaGetSymbolAddress(&p, g_W1h); __half* W1h = (__half*)p;
    cudaGetSymbolAddress(&p, g_W2h); __half* W2h = (__half*)p;

    if (has_ld) {
        prep_kernel<<<PREP_GRID, 1024>>>(x, duration, c1w, c2w, xh, W1h, W2h,
                                         out_dur, out_mel, has_dur, has_mel);

        cudaFuncSetAttribute(mma_conv_ln_kernel<1>,
                             cudaFuncAttributeMaxDynamicSharedMemorySize, 81920);
        cudaFuncSetAttribute(mma_conv_ln_kernel<2>,
                             cudaFuncAttributeMaxDynamicSharedMemorySize, 81920);

        mma_conv_ln_kernel<1><<<GEMM_BLOCKS + GATHER_PER_GEMM, 256, 81920>>>(
            xh, W1h, c1b, l1g, l1b, nullptr, nullptr, nullptr,
            h1h, nullptr, x, out, 0);
        mma_conv_ln_kernel<2><<<GEMM_BLOCKS + GATHER_PER_GEMM, 256, 81920>>>(
            h1h, W2h, c2b, l2g, l2b, lw, lb, mask,
            nullptr, out_ld, x, out, GATHER_PER_GEMM);
    } else {
        prep_kernel<<<32, 1024>>>(x, duration, c1w, c2w, xh, W1h, W2h,
                                  out_dur, out_mel, has_dur, has_mel);
        gather_kernel<<<BB * 16, 256>>>(x, out);
    }
}